// round 1
// baseline (speedup 1.0000x reference)
#include <cuda_runtime.h>
#include <math.h>

// Problem dims
#define V_ 32000
#define E_ 1024
#define H_ 16
#define F_ 4096
#define L_ 4
#define T_ 2048
#define B_ 2
#define D_ 64
#define M_ (B_*T_)   // 4096 rows (B*T)

// Scratch (device globals; allocation APIs are forbidden)
__device__ float g_h [M_*E_];
__device__ float g_xn[M_*E_];
__device__ float g_q [M_*E_];
__device__ float g_k [M_*E_];
__device__ float g_v [M_*E_];
__device__ float g_o [M_*E_];
__device__ float g_mlp[M_*F_];

// ---------------------------------------------------------------------------
// Embedding: h[b,t,:] = tok_emb[x[b,t],:] + pos_emb[t,:]
// ---------------------------------------------------------------------------
__global__ void embed_kernel(const int* __restrict__ x,
                             const float* __restrict__ tok,
                             const float* __restrict__ pos,
                             float* __restrict__ h) {
    int i = blockIdx.x * 256 + threadIdx.x;     // over M_*E_
    int row = i >> 10;                           // /E_
    int e   = i & 1023;
    int tkn = x[row];
    int t   = row & (T_ - 1);                    // row % T_
    h[i] = tok[(size_t)tkn * E_ + e] + pos[(size_t)t * E_ + e];
}

// ---------------------------------------------------------------------------
// LayerNorm: one block (256 threads) per row of E_=1024
// ---------------------------------------------------------------------------
__global__ __launch_bounds__(256) void ln_kernel(const float* __restrict__ in,
                                                 const float* __restrict__ gam,
                                                 const float* __restrict__ bet,
                                                 float* __restrict__ out) {
    int row = blockIdx.x;
    const float* xr = in + (size_t)row * E_;
    float v0[4];
    float s = 0.f;
#pragma unroll
    for (int i = 0; i < 4; i++) { v0[i] = xr[threadIdx.x + 256 * i]; s += v0[i]; }

    __shared__ float sh[8];
    // --- sum reduce ---
    float t = s;
#pragma unroll
    for (int o = 16; o > 0; o >>= 1) t += __shfl_xor_sync(0xffffffffu, t, o);
    if ((threadIdx.x & 31) == 0) sh[threadIdx.x >> 5] = t;
    __syncthreads();
    float tot = 0.f;
#pragma unroll
    for (int i = 0; i < 8; i++) tot += sh[i];
    float mean = tot * (1.0f / E_);

    float vs = 0.f;
#pragma unroll
    for (int i = 0; i < 4; i++) { float d = v0[i] - mean; vs += d * d; }
    __syncthreads();    // sh reuse
    t = vs;
#pragma unroll
    for (int o = 16; o > 0; o >>= 1) t += __shfl_xor_sync(0xffffffffu, t, o);
    if ((threadIdx.x & 31) == 0) sh[threadIdx.x >> 5] = t;
    __syncthreads();
    tot = 0.f;
#pragma unroll
    for (int i = 0; i < 8; i++) tot += sh[i];
    float rstd = rsqrtf(tot * (1.0f / E_) + 1e-5f);

#pragma unroll
    for (int i = 0; i < 4; i++) {
        int e = threadIdx.x + 256 * i;
        out[(size_t)row * E_ + e] = (v0[i] - mean) * rstd * gam[e] + bet[e];
    }
}

// ---------------------------------------------------------------------------
// SGEMM: C[M,N] = A[M,K] @ B[K,N] + bias  (B row-major, [in,out] layout)
// EPI: 0 = plain, 1 = gelu(exact), 2 = += residual
// Block 128x128, BK=8, 256 threads, 8x8 microtile split as 2x2 of 4x4.
// Assumes M%128==0, N%128==0, K%8==0 (true for all calls here).
// ---------------------------------------------------------------------------
__device__ __forceinline__ float gelu_exact(float x) {
    return 0.5f * x * (1.0f + erff(x * 0.70710678118654752f));
}

template<int EPI>
__global__ __launch_bounds__(256) void sgemm_kernel(
    const float* __restrict__ A, const float* __restrict__ Bm,
    const float* __restrict__ bias, const float* __restrict__ res,
    float* __restrict__ C, int M, int N, int K) {
    __shared__ float As[8][128];
    __shared__ float Bs[8][128];

    int bm = blockIdx.y * 128;
    int bn = blockIdx.x * 128;
    int tid = threadIdx.x;

    // global load mapping
    int arow = tid >> 1;            // 0..127
    int acol = (tid & 1) << 2;      // 0 or 4
    int brow = tid >> 5;            // 0..7
    int bcol = (tid & 31) << 2;     // 0..124
    const float* Aptr = A + (size_t)(bm + arow) * K + acol;
    const float* Bptr = Bm + (size_t)brow * N + bn + bcol;

    // compute mapping
    int ty = (tid >> 4) << 2;       // 0..60, rows {ty..ty+3, ty+64..ty+67}
    int tx = (tid & 15) << 2;       // 0..60, cols {tx..tx+3, tx+64..tx+67}

    float acc[8][8];
#pragma unroll
    for (int i = 0; i < 8; i++)
#pragma unroll
        for (int j = 0; j < 8; j++) acc[i][j] = 0.f;

    for (int k0 = 0; k0 < K; k0 += 8) {
        float4 av = *(const float4*)(Aptr + k0);
        As[acol + 0][arow] = av.x;
        As[acol + 1][arow] = av.y;
        As[acol + 2][arow] = av.z;
        As[acol + 3][arow] = av.w;
        *(float4*)&Bs[brow][bcol] = *(const float4*)(Bptr + (size_t)k0 * N);
        __syncthreads();

#pragma unroll
        for (int kk = 0; kk < 8; kk++) {
            float4 a0 = *(const float4*)&As[kk][ty];
            float4 a1 = *(const float4*)&As[kk][ty + 64];
            float4 b0 = *(const float4*)&Bs[kk][tx];
            float4 b1 = *(const float4*)&Bs[kk][tx + 64];
            float a[8] = {a0.x, a0.y, a0.z, a0.w, a1.x, a1.y, a1.z, a1.w};
            float b[8] = {b0.x, b0.y, b0.z, b0.w, b1.x, b1.y, b1.z, b1.w};
#pragma unroll
            for (int i = 0; i < 8; i++)
#pragma unroll
                for (int j = 0; j < 8; j++) acc[i][j] += a[i] * b[j];
        }
        __syncthreads();
    }

    // Epilogue
#pragma unroll
    for (int ri = 0; ri < 2; ri++) {
#pragma unroll
        for (int i = 0; i < 4; i++) {
            int row = bm + ri * 64 + ty + i;
#pragma unroll
            for (int ci = 0; ci < 2; ci++) {
                int col = bn + ci * 64 + tx;
                float4 bi = *(const float4*)&bias[col];
                float r0 = acc[ri * 4 + i][ci * 4 + 0] + bi.x;
                float r1 = acc[ri * 4 + i][ci * 4 + 1] + bi.y;
                float r2 = acc[ri * 4 + i][ci * 4 + 2] + bi.z;
                float r3 = acc[ri * 4 + i][ci * 4 + 3] + bi.w;
                if (EPI == 1) {
                    r0 = gelu_exact(r0); r1 = gelu_exact(r1);
                    r2 = gelu_exact(r2); r3 = gelu_exact(r3);
                }
                if (EPI == 2) {
                    float4 rv = *(const float4*)&res[(size_t)row * N + col];
                    r0 += rv.x; r1 += rv.y; r2 += rv.z; r3 += rv.w;
                }
                *(float4*)&C[(size_t)row * N + col] = make_float4(r0, r1, r2, r3);
            }
        }
    }
}

// ---------------------------------------------------------------------------
// Causal flash attention, fp32. Layout: q/k/v/o are [B, T, H, D] contiguous.
// One block per (b, h, 64-row query tile); 64 threads, 1 query row / thread.
// Key tiles of 32 rows staged in shared; broadcast LDS.128 reads.
// ---------------------------------------------------------------------------
__global__ __launch_bounds__(64) void attn_kernel(const float* __restrict__ q,
                                                  const float* __restrict__ k,
                                                  const float* __restrict__ v,
                                                  float* __restrict__ o) {
    __shared__ float Ks[32][64];
    __shared__ float Vs[32][64];

    int qt = blockIdx.x & 31;           // query tile (T_/64 = 32)
    int bh = blockIdx.x >> 5;
    int b  = bh >> 4;                   // /H_
    int hh = bh & 15;
    int row = qt * 64 + threadIdx.x;

    const float scale = 0.125f;         // 1/sqrt(64)
    float qr[64];
    const float* qp = q + ((size_t)(b * T_ + row) * H_ + hh) * D_;
#pragma unroll
    for (int d = 0; d < 64; d++) qr[d] = qp[d] * scale;

    float acc[64];
#pragma unroll
    for (int d = 0; d < 64; d++) acc[d] = 0.f;
    float m = -1e30f, l = 0.f;

    int nt = qt * 2 + 2;                // key tiles needed (32 keys each)
    for (int kt = 0; kt < nt; kt++) {
        int kb = kt * 32;
        // cooperative tile load: 2048 floats per array, 8 float4 per thread
        {
            int t = threadIdx.x;
#pragma unroll
            for (int i = 0; i < 8; i++) {
                int idx = (i * 64 + t) * 4;      // 0..2044
                int r = idx >> 6;
                int c = idx & 63;
                size_t goff = ((size_t)(b * T_ + kb + r) * H_ + hh) * D_ + c;
                *(float4*)&Ks[r][c] = *(const float4*)(k + goff);
                *(float4*)&Vs[r][c] = *(const float4*)(v + goff);
            }
        }
        __syncthreads();

        float s[32];
        float tmax = -1e30f;
#pragma unroll
        for (int c = 0; c < 32; c++) {
            if (kb + c <= row) {
                float sc = 0.f;
#pragma unroll
                for (int d = 0; d < 64; d += 4) {
                    float4 kv = *(const float4*)&Ks[c][d];
                    sc += qr[d] * kv.x + qr[d + 1] * kv.y
                        + qr[d + 2] * kv.z + qr[d + 3] * kv.w;
                }
                s[c] = sc;
                tmax = fmaxf(tmax, sc);
            } else {
                s[c] = -1e30f;
            }
        }
        float mnew = fmaxf(m, tmax);
        float corr = __expf(m - mnew);
        l *= corr;
#pragma unroll
        for (int d = 0; d < 64; d++) acc[d] *= corr;
#pragma unroll
        for (int c = 0; c < 32; c++) {
            float p = (kb + c <= row) ? __expf(s[c] - mnew) : 0.f;
            l += p;
#pragma unroll
            for (int d = 0; d < 64; d += 4) {
                float4 vv = *(const float4*)&Vs[c][d];
                acc[d]     += p * vv.x;
                acc[d + 1] += p * vv.y;
                acc[d + 2] += p * vv.z;
                acc[d + 3] += p * vv.w;
            }
        }
        m = mnew;
        __syncthreads();
    }

    float inv = 1.0f / l;
    float* op = o + ((size_t)(b * T_ + row) * H_ + hh) * D_;
#pragma unroll
    for (int d = 0; d < 64; d++) op[d] = acc[d] * inv;
}

// ---------------------------------------------------------------------------
// Host orchestration
// ---------------------------------------------------------------------------
extern "C" void kernel_launch(void* const* d_in, const int* in_sizes, int n_in,
                              void* d_out, int out_size) {
    const int*   x    = (const int*)  d_in[0];
    const float* tok  = (const float*)d_in[1];
    const float* pos  = (const float*)d_in[2];
    const float* Wq   = (const float*)d_in[3];
    const float* bq   = (const float*)d_in[4];
    const float* Wk   = (const float*)d_in[5];
    const float* bk   = (const float*)d_in[6];
    const float* Wv   = (const float*)d_in[7];
    const float* bv   = (const float*)d_in[8];
    const float* Wo   = (const float*)d_in[9];
    const float* bo   = (const float*)d_in[10];
    const float* ln1g = (const float*)d_in[11];
    const float* ln1b = (const float*)d_in[12];
    const float* W1   = (const float*)d_in[13];
    const float* b1   = (const float*)d_in[14];
    const float* W2   = (const float*)d_in[15];
    const float* b2   = (const float*)d_in[16];
    const float* ln2g = (const float*)d_in[17];
    const float* ln2b = (const float*)d_in[18];
    const float* lnfg = (const float*)d_in[19];
    const float* lnfb = (const float*)d_in[20];
    const float* Wout = (const float*)d_in[21];
    const float* bout = (const float*)d_in[22];
    float* out = (float*)d_out;

    float *h, *xn, *q, *k, *v, *o, *mlp;
    cudaGetSymbolAddress((void**)&h,   g_h);
    cudaGetSymbolAddress((void**)&xn,  g_xn);
    cudaGetSymbolAddress((void**)&q,   g_q);
    cudaGetSymbolAddress((void**)&k,   g_k);
    cudaGetSymbolAddress((void**)&v,   g_v);
    cudaGetSymbolAddress((void**)&o,   g_o);
    cudaGetSymbolAddress((void**)&mlp, g_mlp);

    dim3 gEE(E_ / 128, M_ / 128);   // N=1024
    dim3 gEF(F_ / 128, M_ / 128);   // N=4096
    dim3 gEV(V_ / 128, M_ / 128);   // N=32000

    embed_kernel<<<(M_ * E_) / 256, 256>>>(x, tok, pos, h);

    for (int l = 0; l < L_; l++) {
        const float* wq = Wq + (size_t)l * E_ * E_;
        const float* wk = Wk + (size_t)l * E_ * E_;
        const float* wv = Wv + (size_t)l * E_ * E_;
        const float* wo = Wo + (size_t)l * E_ * E_;
        const float* w1 = W1 + (size_t)l * E_ * F_;
        const float* w2 = W2 + (size_t)l * F_ * E_;

        ln_kernel<<<M_, 256>>>(h, ln1g + l * E_, ln1b + l * E_, xn);
        sgemm_kernel<0><<<gEE, 256>>>(xn, wq, bq + l * E_, nullptr, q, M_, E_, E_);
        sgemm_kernel<0><<<gEE, 256>>>(xn, wk, bk + l * E_, nullptr, k, M_, E_, E_);
        sgemm_kernel<0><<<gEE, 256>>>(xn, wv, bv + l * E_, nullptr, v, M_, E_, E_);
        attn_kernel<<<B_ * H_ * (T_ / 64), 64>>>(q, k, v, o);
        sgemm_kernel<2><<<gEE, 256>>>(o, wo, bo + l * E_, h, h, M_, E_, E_);
        ln_kernel<<<M_, 256>>>(h, ln2g + l * E_, ln2b + l * E_, xn);
        sgemm_kernel<1><<<gEF, 256>>>(xn, w1, b1 + l * F_, nullptr, mlp, M_, F_, E_);
        sgemm_kernel<2><<<gEE, 256>>>(mlp, w2, b2 + l * E_, h, h, M_, E_, F_);
    }

    ln_kernel<<<M_, 256>>>(h, lnfg, lnfb, xn);
    sgemm_kernel<0><<<gEV, 256>>>(xn, Wout, bout, nullptr, out, M_, V_, E_);
}

// round 3
// speedup vs baseline: 1.5768x; 1.5768x over previous
#include <cuda_runtime.h>
#include <cuda_bf16.h>
#include <math.h>
#include <stdint.h>

// Problem dims
#define V_ 32000
#define E_ 1024
#define H_ 16
#define F_ 4096
#define L_ 4
#define T_ 2048
#define B_ 2
#define D_ 64
#define M_ (B_*T_)   // 4096

typedef __nv_bfloat16 bf16;

// ---------------------------------------------------------------------------
// Scratch (device globals; allocation APIs are forbidden)
// ---------------------------------------------------------------------------
__device__ float g_h  [M_*E_];
__device__ float g_qkv[M_*3*E_];
__device__ float g_bqkv[L_*3*E_];
__device__ bf16 g_xn_hi [M_*E_], g_xn_lo [M_*E_];
__device__ bf16 g_o_hi  [M_*E_], g_o_lo  [M_*E_];
__device__ bf16 g_mlp_hi[M_*F_], g_mlp_lo[M_*F_];
__device__ bf16 g_qkvT_hi[L_*3*E_*E_], g_qkvT_lo[L_*3*E_*E_];
__device__ bf16 g_woT_hi [L_*E_*E_],   g_woT_lo [L_*E_*E_];
__device__ bf16 g_w1T_hi [L_*F_*E_],   g_w1T_lo [L_*F_*E_];
__device__ bf16 g_w2T_hi [L_*E_*F_],   g_w2T_lo [L_*E_*F_];
__device__ bf16 g_woutT_hi[(size_t)V_*E_], g_woutT_lo[(size_t)V_*E_];

// ---------------------------------------------------------------------------
// PTX helpers
// ---------------------------------------------------------------------------
__device__ __forceinline__ uint32_t smem_u32(const void* p) {
    uint32_t a;
    asm("{ .reg .u64 t; cvta.to.shared.u64 t, %1; cvt.u32.u64 %0, t; }" : "=r"(a) : "l"(p));
    return a;
}
static __device__ __forceinline__ void cpa16(uint32_t s, const void* g) {
    asm volatile("cp.async.cg.shared.global [%0], [%1], 16;" :: "r"(s), "l"(g) : "memory");
}
#define CP_COMMIT() asm volatile("cp.async.commit_group;" ::: "memory")
#define CP_WAIT2()  asm volatile("cp.async.wait_group 2;" ::: "memory")

struct Frag4 { uint32_t x, y, z, w; };

static __device__ __forceinline__ Frag4 ldsm_x4(uint32_t addr) {
    Frag4 r;
    asm volatile("ldmatrix.sync.aligned.m8n8.x4.shared.b16 {%0,%1,%2,%3}, [%4];"
                 : "=r"(r.x), "=r"(r.y), "=r"(r.z), "=r"(r.w) : "r"(addr));
    return r;
}

static __device__ __forceinline__ void mma_bf16(float* c, const Frag4& a,
                                                uint32_t b0, uint32_t b1) {
    asm volatile(
        "mma.sync.aligned.m16n8k16.row.col.f32.bf16.bf16.f32 "
        "{%0,%1,%2,%3}, {%4,%5,%6,%7}, {%8,%9}, {%0,%1,%2,%3};"
        : "+f"(c[0]), "+f"(c[1]), "+f"(c[2]), "+f"(c[3])
        : "r"(a.x), "r"(a.y), "r"(a.z), "r"(a.w), "r"(b0), "r"(b1));
}

__device__ __forceinline__ float gelu_exact(float x) {
    return 0.5f * x * (1.0f + erff(x * 0.70710678118654752f));
}

// ---------------------------------------------------------------------------
// HMMA GEMM: C[M,N] = (Ahi+Alo)[M,K] @ (Bhi+Blo)^T  (B stored [N,K], K-contig)
// 3-term split: AhiBhi + AhiBlo + AloBhi, fp32 accum.
// BM=128 BN=128 BK=32, 4-stage cp.async, 256 threads (8 warps, 2x4),
// warptile 64x32 (4x4 m16n8k16 tiles). Rows padded to 80B (conflict-free).
// EPI: 0 = fp32 +bias ; 1 = gelu -> bf16 hi/lo ; 2 = fp32 +bias +residual
// ---------------------------------------------------------------------------
#define ROWB      80
#define TILE_B    (128 * ROWB)       // 10240
#define OFF_AHI   0
#define OFF_ALO   (1 * TILE_B)
#define OFF_BHI   (2 * TILE_B)
#define OFF_BLO   (3 * TILE_B)
#define STAGE_B   (4 * TILE_B)       // 40960
#define NSTAGE    4
#define GSMEM_SZ  (NSTAGE * STAGE_B) // 163840

static __device__ __forceinline__ void load_stage(
    uint32_t st, const bf16* __restrict__ Ahi, const bf16* __restrict__ Alo,
    const bf16* __restrict__ Bhi, const bf16* __restrict__ Blo,
    int bm, int bn, int k0, int K, int tid)
{
#pragma unroll
    for (int i = 0; i < 2; i++) {
        int c = tid + (i << 8);          // 0..511
        int r = c >> 2, q = c & 3;
        uint32_t so = (uint32_t)(r * ROWB + q * 16);
        size_t ga = (size_t)(bm + r) * K + k0 + (q << 3);
        size_t gb = (size_t)(bn + r) * K + k0 + (q << 3);
        cpa16(st + OFF_AHI + so, Ahi + ga);
        cpa16(st + OFF_ALO + so, Alo + ga);
        cpa16(st + OFF_BHI + so, Bhi + gb);
        cpa16(st + OFF_BLO + so, Blo + gb);
    }
}

template<int EPI>
__global__ __launch_bounds__(256, 1) void tgemm_kernel(
    const bf16* __restrict__ Ahi, const bf16* __restrict__ Alo,
    const bf16* __restrict__ Bhi, const bf16* __restrict__ Blo,
    const float* __restrict__ bias, const float* __restrict__ res,
    float* __restrict__ Cf, bf16* __restrict__ Chi, bf16* __restrict__ Clo,
    int N, int K)
{
    extern __shared__ __align__(1024) unsigned char smem[];
    uint32_t sb = smem_u32(smem);
    int tid = threadIdx.x, wid = tid >> 5, lane = tid & 31;
    int bm = blockIdx.x * 128, bn = blockIdx.y * 128;
    int wm = wid & 1, wn = wid >> 1;

    // lane-invariant parts of ldmatrix addresses
    uint32_t a_lane = (uint32_t)((wm * 64 + (lane & 15)) * ROWB + ((lane >> 4) << 4));
    uint32_t b_lane = (uint32_t)((wn * 32 + (lane & 7) + ((lane >> 4) << 3)) * ROWB
                                 + (((lane >> 3) & 1) << 4));

    float acc[4][4][4];
#pragma unroll
    for (int i = 0; i < 4; i++)
#pragma unroll
        for (int j = 0; j < 4; j++)
#pragma unroll
            for (int e = 0; e < 4; e++) acc[i][j][e] = 0.f;

    int nk = K >> 5;
    // prefetch NSTAGE-1 stages
#pragma unroll
    for (int s = 0; s < NSTAGE - 1; s++) {
        load_stage(sb + s * STAGE_B, Ahi, Alo, Bhi, Blo, bm, bn, s << 5, K, tid);
        CP_COMMIT();
    }

    for (int kt = 0; kt < nk; kt++) {
        CP_WAIT2();
        __syncthreads();

        // prefetch future stage into the slot freed last iteration
        int kf = kt + NSTAGE - 1;
        if (kf < nk)
            load_stage(sb + (kf & (NSTAGE - 1)) * STAGE_B,
                       Ahi, Alo, Bhi, Blo, bm, bn, kf << 5, K, tid);
        CP_COMMIT();

        uint32_t st = sb + (kt & (NSTAGE - 1)) * STAGE_B;
#pragma unroll
        for (int ks = 0; ks < 2; ks++) {
            uint32_t kb = ks << 5;   // 16 bf16 = 32 bytes
            Frag4 ah[4], al[4];
#pragma unroll
            for (int mt = 0; mt < 4; mt++) {
                uint32_t ao = st + a_lane + mt * (16 * ROWB) + kb;
                ah[mt] = ldsm_x4(ao + OFF_AHI);
                al[mt] = ldsm_x4(ao + OFF_ALO);
            }
            Frag4 bh[2], bl[2];
#pragma unroll
            for (int np = 0; np < 2; np++) {
                uint32_t bo = st + b_lane + np * (16 * ROWB) + kb;
                bh[np] = ldsm_x4(bo + OFF_BHI);
                bl[np] = ldsm_x4(bo + OFF_BLO);
            }
#pragma unroll
            for (int mt = 0; mt < 4; mt++) {
#pragma unroll
                for (int nt = 0; nt < 4; nt++) {
                    uint32_t b0h = (nt & 1) ? bh[nt >> 1].z : bh[nt >> 1].x;
                    uint32_t b1h = (nt & 1) ? bh[nt >> 1].w : bh[nt >> 1].y;
                    uint32_t b0l = (nt & 1) ? bl[nt >> 1].z : bl[nt >> 1].x;
                    uint32_t b1l = (nt & 1) ? bl[nt >> 1].w : bl[nt >> 1].y;
                    mma_bf16(acc[mt][nt], ah[mt], b0h, b1h);
                    mma_bf16(acc[mt][nt], ah[mt], b0l, b1l);
                    mma_bf16(acc[mt][nt], al[mt], b0h, b1h);
                }
            }
        }
    }
    __syncthreads();

    // Epilogue (register -> global, no bounce)
    int row_in = lane >> 2;
    int col2   = (lane & 3) << 1;
#pragma unroll
    for (int mt = 0; mt < 4; mt++) {
#pragma unroll
        for (int nt = 0; nt < 4; nt++) {
            int col = bn + wn * 32 + nt * 8 + col2;
            float bx = __ldg(&bias[col]), by = __ldg(&bias[col + 1]);
#pragma unroll
            for (int half = 0; half < 2; half++) {
                int row = bm + wm * 64 + mt * 16 + row_in + half * 8;
                size_t off = (size_t)row * N + col;
                float v0 = acc[mt][nt][half * 2 + 0] + bx;
                float v1 = acc[mt][nt][half * 2 + 1] + by;
                if (EPI == 0) {
                    *(float2*)&Cf[off] = make_float2(v0, v1);
                } else if (EPI == 1) {
                    float g0 = gelu_exact(v0), g1 = gelu_exact(v1);
                    bf16 h0 = __float2bfloat16(g0), h1 = __float2bfloat16(g1);
                    __nv_bfloat162 hh; hh.x = h0; hh.y = h1;
                    __nv_bfloat162 ll;
                    ll.x = __float2bfloat16(g0 - __bfloat162float(h0));
                    ll.y = __float2bfloat16(g1 - __bfloat162float(h1));
                    *(__nv_bfloat162*)&Chi[off] = hh;
                    *(__nv_bfloat162*)&Clo[off] = ll;
                } else {
                    float2 rv = *(const float2*)&res[off];
                    *(float2*)&Cf[off] = make_float2(v0 + rv.x, v1 + rv.y);
                }
            }
        }
    }
}

// ---------------------------------------------------------------------------
// Weight transpose + bf16 hi/lo split: W[K,N] (N contig) -> T[N,K] (K contig)
// ---------------------------------------------------------------------------
__global__ void wconv_kernel(const float* __restrict__ W,
                             bf16* __restrict__ Th, bf16* __restrict__ Tl,
                             int K, int N, size_t inLs, size_t outLs)
{
    __shared__ float t[32][33];
    const float* Wl = W + blockIdx.z * inLs;
    Th += blockIdx.z * outLs;
    Tl += blockIdx.z * outLs;
    int n0 = blockIdx.x * 32, k0 = blockIdx.y * 32;
    int tx = threadIdx.x, ty = threadIdx.y;
#pragma unroll
    for (int i = 0; i < 4; i++)
        t[ty + 8 * i][tx] = Wl[(size_t)(k0 + ty + 8 * i) * N + n0 + tx];
    __syncthreads();
#pragma unroll
    for (int i = 0; i < 4; i++) {
        int n = ty + 8 * i;
        float v = t[tx][n];
        bf16 hv = __float2bfloat16(v);
        size_t o = (size_t)(n0 + n) * K + k0 + tx;
        Th[o] = hv;
        Tl[o] = __float2bfloat16(v - __bfloat162float(hv));
    }
}

// Pack per-layer QKV biases into [L, 3E]
__global__ void bpack_kernel(const float* __restrict__ bq, const float* __restrict__ bk,
                             const float* __restrict__ bv, float* __restrict__ out) {
    int i = blockIdx.x * 256 + threadIdx.x;
    int l = i / 3072, j = i % 3072;
    float v = (j < 1024) ? bq[l * 1024 + j]
            : (j < 2048) ? bk[l * 1024 + j - 1024]
                         : bv[l * 1024 + j - 2048];
    out[i] = v;
}

// ---------------------------------------------------------------------------
// Embedding
// ---------------------------------------------------------------------------
__global__ void embed_kernel(const int* __restrict__ x, const float* __restrict__ tok,
                             const float* __restrict__ pos, float* __restrict__ h) {
    int i = blockIdx.x * 256 + threadIdx.x;
    int row = i >> 10, e = i & 1023;
    int tkn = x[row];
    int t = row & (T_ - 1);
    h[i] = tok[(size_t)tkn * E_ + e] + pos[(size_t)t * E_ + e];
}

// ---------------------------------------------------------------------------
// LayerNorm -> bf16 hi/lo
// ---------------------------------------------------------------------------
__global__ __launch_bounds__(256) void ln_kernel(const float* __restrict__ in,
                                                 const float* __restrict__ gam,
                                                 const float* __restrict__ bet,
                                                 bf16* __restrict__ outhi,
                                                 bf16* __restrict__ outlo) {
    int row = blockIdx.x;
    const float* xr = in + (size_t)row * E_;
    float v0[4];
    float s = 0.f;
#pragma unroll
    for (int i = 0; i < 4; i++) { v0[i] = xr[threadIdx.x + 256 * i]; s += v0[i]; }

    __shared__ float sh[8];
    float t = s;
#pragma unroll
    for (int o = 16; o > 0; o >>= 1) t += __shfl_xor_sync(0xffffffffu, t, o);
    if ((threadIdx.x & 31) == 0) sh[threadIdx.x >> 5] = t;
    __syncthreads();
    float tot = 0.f;
#pragma unroll
    for (int i = 0; i < 8; i++) tot += sh[i];
    float mean = tot * (1.0f / E_);

    float vs = 0.f;
#pragma unroll
    for (int i = 0; i < 4; i++) { float d = v0[i] - mean; vs += d * d; }
    __syncthreads();
    t = vs;
#pragma unroll
    for (int o = 16; o > 0; o >>= 1) t += __shfl_xor_sync(0xffffffffu, t, o);
    if ((threadIdx.x & 31) == 0) sh[threadIdx.x >> 5] = t;
    __syncthreads();
    tot = 0.f;
#pragma unroll
    for (int i = 0; i < 8; i++) tot += sh[i];
    float rstd = rsqrtf(tot * (1.0f / E_) + 1e-5f);

#pragma unroll
    for (int i = 0; i < 4; i++) {
        int e = threadIdx.x + 256 * i;
        float y = (v0[i] - mean) * rstd * gam[e] + bet[e];
        bf16 hv = __float2bfloat16(y);
        size_t o = (size_t)row * E_ + e;
        outhi[o] = hv;
        outlo[o] = __float2bfloat16(y - __bfloat162float(hv));
    }
}

// ---------------------------------------------------------------------------
// Causal flash attention, fp32. qkv packed [M, 3E]; out -> bf16 hi/lo [M, E]
// ---------------------------------------------------------------------------
__global__ __launch_bounds__(64) void attn_kernel(const float* __restrict__ qkv,
                                                  bf16* __restrict__ ohi,
                                                  bf16* __restrict__ olo) {
    __shared__ float Ks[32][64];
    __shared__ float Vs[32][64];

    int qt = blockIdx.x & 31;
    int bh = blockIdx.x >> 5;
    int b  = bh >> 4;
    int hh = bh & 15;
    int row = qt * 64 + threadIdx.x;

    const float scale = 0.125f;
    float qr[64];
    const float* qp = qkv + (size_t)(b * T_ + row) * 3072 + hh * 64;
#pragma unroll
    for (int d = 0; d < 64; d++) qr[d] = qp[d] * scale;

    float acc[64];
#pragma unroll
    for (int d = 0; d < 64; d++) acc[d] = 0.f;
    float m = -1e30f, l = 0.f;

    int nt = qt * 2 + 2;
    for (int kt = 0; kt < nt; kt++) {
        int kb = kt * 32;
        {
            int tt = threadIdx.x;
#pragma unroll
            for (int i = 0; i < 8; i++) {
                int idx = (i * 64 + tt) * 4;
                int r = idx >> 6, c = idx & 63;
                size_t base = (size_t)(b * T_ + kb + r) * 3072 + hh * 64 + c;
                *(float4*)&Ks[r][c] = *(const float4*)(qkv + base + 1024);
                *(float4*)&Vs[r][c] = *(const float4*)(qkv + base + 2048);
            }
        }
        __syncthreads();

        float sv[32];
        float tmax = -1e30f;
#pragma unroll
        for (int c = 0; c < 32; c++) {
            if (kb + c <= row) {
                float sc = 0.f;
#pragma unroll
                for (int d = 0; d < 64; d += 4) {
                    float4 kv = *(const float4*)&Ks[c][d];
                    sc += qr[d] * kv.x + qr[d+1] * kv.y + qr[d+2] * kv.z + qr[d+3] * kv.w;
                }
                sv[c] = sc;
                tmax = fmaxf(tmax, sc);
            } else sv[c] = -1e30f;
        }
        float mnew = fmaxf(m, tmax);
        float corr = __expf(m - mnew);
        l *= corr;
#pragma unroll
        for (int d = 0; d < 64; d++) acc[d] *= corr;
#pragma unroll
        for (int c = 0; c < 32; c++) {
            float p = (kb + c <= row) ? __expf(sv[c] - mnew) : 0.f;
            l += p;
#pragma unroll
            for (int d = 0; d < 64; d += 4) {
                float4 vv = *(const float4*)&Vs[c][d];
                acc[d]   += p * vv.x;  acc[d+1] += p * vv.y;
                acc[d+2] += p * vv.z;  acc[d+3] += p * vv.w;
            }
        }
        m = mnew;
        __syncthreads();
    }

    float inv = 1.0f / l;
    size_t ob = (size_t)(b * T_ + row) * E_ + hh * 64;
#pragma unroll
    for (int d = 0; d < 64; d++) {
        float y = acc[d] * inv;
        bf16 hv = __float2bfloat16(y);
        ohi[ob + d] = hv;
        olo[ob + d] = __float2bfloat16(y - __bfloat162float(hv));
    }
}

// ---------------------------------------------------------------------------
// Host orchestration
// ---------------------------------------------------------------------------
extern "C" void kernel_launch(void* const* d_in, const int* in_sizes, int n_in,
                              void* d_out, int out_size) {
    const int*   x    = (const int*)  d_in[0];
    const float* tok  = (const float*)d_in[1];
    const float* pos  = (const float*)d_in[2];
    const float* Wq   = (const float*)d_in[3];
    const float* bq   = (const float*)d_in[4];
    const float* Wk   = (const float*)d_in[5];
    const float* bk   = (const float*)d_in[6];
    const float* Wv   = (const float*)d_in[7];
    const float* bv   = (const float*)d_in[8];
    const float* Wo   = (const float*)d_in[9];
    const float* bo   = (const float*)d_in[10];
    const float* ln1g = (const float*)d_in[11];
    const float* ln1b = (const float*)d_in[12];
    const float* W1   = (const float*)d_in[13];
    const float* b1   = (const float*)d_in[14];
    const float* W2   = (const float*)d_in[15];
    const float* b2   = (const float*)d_in[16];
    const float* ln2g = (const float*)d_in[17];
    const float* ln2b = (const float*)d_in[18];
    const float* lnfg = (const float*)d_in[19];
    const float* lnfb = (const float*)d_in[20];
    const float* Wout = (const float*)d_in[21];
    const float* bout = (const float*)d_in[22];
    float* out = (float*)d_out;

    float *h, *qkv, *bqkv;
    bf16 *xnh, *xnl, *oh, *ol, *mph, *mpl;
    bf16 *qkvTh, *qkvTl, *woTh, *woTl, *w1Th, *w1Tl, *w2Th, *w2Tl, *wouTh, *wouTl;
    cudaGetSymbolAddress((void**)&h,    g_h);
    cudaGetSymbolAddress((void**)&qkv,  g_qkv);
    cudaGetSymbolAddress((void**)&bqkv, g_bqkv);
    cudaGetSymbolAddress((void**)&xnh,  g_xn_hi);  cudaGetSymbolAddress((void**)&xnl, g_xn_lo);
    cudaGetSymbolAddress((void**)&oh,   g_o_hi);   cudaGetSymbolAddress((void**)&ol,  g_o_lo);
    cudaGetSymbolAddress((void**)&mph,  g_mlp_hi); cudaGetSymbolAddress((void**)&mpl, g_mlp_lo);
    cudaGetSymbolAddress((void**)&qkvTh, g_qkvT_hi); cudaGetSymbolAddress((void**)&qkvTl, g_qkvT_lo);
    cudaGetSymbolAddress((void**)&woTh,  g_woT_hi);  cudaGetSymbolAddress((void**)&woTl,  g_woT_lo);
    cudaGetSymbolAddress((void**)&w1Th,  g_w1T_hi);  cudaGetSymbolAddress((void**)&w1Tl,  g_w1T_lo);
    cudaGetSymbolAddress((void**)&w2Th,  g_w2T_hi);  cudaGetSymbolAddress((void**)&w2Tl,  g_w2T_lo);
    cudaGetSymbolAddress((void**)&wouTh, g_woutT_hi); cudaGetSymbolAddress((void**)&wouTl, g_woutT_lo);

    cudaFuncSetAttribute(tgemm_kernel<0>, cudaFuncAttributeMaxDynamicSharedMemorySize, GSMEM_SZ);
    cudaFuncSetAttribute(tgemm_kernel<1>, cudaFuncAttributeMaxDynamicSharedMemorySize, GSMEM_SZ);
    cudaFuncSetAttribute(tgemm_kernel<2>, cudaFuncAttributeMaxDynamicSharedMemorySize, GSMEM_SZ);

    const size_t EE = (size_t)E_ * E_, EF = (size_t)E_ * F_;
    dim3 tb(32, 8);
    wconv_kernel<<<dim3(32, 32, L_), tb>>>(Wq, qkvTh,          qkvTl,          E_, E_, EE, 3 * EE);
    wconv_kernel<<<dim3(32, 32, L_), tb>>>(Wk, qkvTh + EE,     qkvTl + EE,     E_, E_, EE, 3 * EE);
    wconv_kernel<<<dim3(32, 32, L_), tb>>>(Wv, qkvTh + 2 * EE, qkvTl + 2 * EE, E_, E_, EE, 3 * EE);
    wconv_kernel<<<dim3(32, 32, L_), tb>>>(Wo, woTh, woTl, E_, E_, EE, EE);
    wconv_kernel<<<dim3(128, 32, L_), tb>>>(W1, w1Th, w1Tl, E_, F_, EF, EF);
    wconv_kernel<<<dim3(32, 128, L_), tb>>>(W2, w2Th, w2Tl, F_, E_, EF, EF);
    wconv_kernel<<<dim3(1000, 32, 1), tb>>>(Wout, wouTh, wouTl, E_, V_, 0, 0);
    bpack_kernel<<<(L_ * 3 * E_) / 256, 256>>>(bq, bk, bv, bqkv);

    embed_kernel<<<(M_ * E_) / 256, 256>>>(x, tok, pos, h);

    for (int l = 0; l < L_; l++) {
        ln_kernel<<<M_, 256>>>(h, ln1g + l * E_, ln1b + l * E_, xnh, xnl);
        tgemm_kernel<0><<<dim3(M_ / 128, 24), 256, GSMEM_SZ>>>(
            xnh, xnl, qkvTh + l * 3 * EE, qkvTl + l * 3 * EE,
            bqkv + l * 3 * E_, nullptr, qkv, nullptr, nullptr, 3 * E_, E_);
        attn_kernel<<<B_ * H_ * (T_ / 64), 64>>>(qkv, oh, ol);
        tgemm_kernel<2><<<dim3(M_ / 128, 8), 256, GSMEM_SZ>>>(
            oh, ol, woTh + l * EE, woTl + l * EE,
            bo + l * E_, h, h, nullptr, nullptr, E_, E_);
        ln_kernel<<<M_, 256>>>(h, ln2g + l * E_, ln2b + l * E_, xnh, xnl);
        tgemm_kernel<1><<<dim3(M_ / 128, 32), 256, GSMEM_SZ>>>(
            xnh, xnl, w1Th + l * EF, w1Tl + l * EF,
            b1 + l * F_, nullptr, nullptr, mph, mpl, F_, E_);
        tgemm_kernel<2><<<dim3(M_ / 128, 8), 256, GSMEM_SZ>>>(
            mph, mpl, w2Th + l * EF, w2Tl + l * EF,
            b2 + l * E_, h, h, nullptr, nullptr, E_, F_);
    }

    ln_kernel<<<M_, 256>>>(h, lnfg, lnfb, xnh, xnl);
    tgemm_kernel<0><<<dim3(M_ / 128, V_ / 128), 256, GSMEM_SZ>>>(
        xnh, xnl, wouTh, wouTl, bout, nullptr, out, nullptr, nullptr, V_, E_);
}

// round 4
// speedup vs baseline: 1.6010x; 1.0153x over previous
#include <cuda_runtime.h>
#include <cuda_bf16.h>
#include <math.h>
#include <stdint.h>

// Problem dims
#define V_ 32000
#define E_ 1024
#define H_ 16
#define F_ 4096
#define L_ 4
#define T_ 2048
#define B_ 2
#define D_ 64
#define M_ (B_*T_)   // 4096

typedef __nv_bfloat16 bf16;

// ---------------------------------------------------------------------------
// Scratch (device globals; allocation APIs are forbidden)
// ---------------------------------------------------------------------------
__device__ float g_h  [M_*E_];
__device__ float g_qkv[M_*3*E_];
__device__ float g_bqkv[L_*3*E_];
__device__ bf16 g_xn_hi [M_*E_], g_xn_lo [M_*E_];
__device__ bf16 g_o_hi  [M_*E_], g_o_lo  [M_*E_];
__device__ bf16 g_mlp_hi[M_*F_], g_mlp_lo[M_*F_];
__device__ bf16 g_qkvT_hi[L_*3*E_*E_], g_qkvT_lo[L_*3*E_*E_];
__device__ bf16 g_woT_hi [L_*E_*E_],   g_woT_lo [L_*E_*E_];
__device__ bf16 g_w1T_hi [L_*F_*E_],   g_w1T_lo [L_*F_*E_];
__device__ bf16 g_w2T_hi [L_*E_*F_],   g_w2T_lo [L_*E_*F_];
__device__ bf16 g_woutT_hi[(size_t)V_*E_], g_woutT_lo[(size_t)V_*E_];

// ---------------------------------------------------------------------------
// PTX helpers
// ---------------------------------------------------------------------------
__device__ __forceinline__ uint32_t smem_u32(const void* p) {
    uint32_t a;
    asm("{ .reg .u64 t; cvta.to.shared.u64 t, %1; cvt.u32.u64 %0, t; }" : "=r"(a) : "l"(p));
    return a;
}
static __device__ __forceinline__ void cpa16(uint32_t s, const void* g) {
    asm volatile("cp.async.cg.shared.global [%0], [%1], 16;" :: "r"(s), "l"(g) : "memory");
}
#define CP_COMMIT() asm volatile("cp.async.commit_group;" ::: "memory")
#define CP_WAIT1()  asm volatile("cp.async.wait_group 1;" ::: "memory")

struct Frag4 { uint32_t x, y, z, w; };

static __device__ __forceinline__ Frag4 ldsm_x4(uint32_t addr) {
    Frag4 r;
    asm volatile("ldmatrix.sync.aligned.m8n8.x4.shared.b16 {%0,%1,%2,%3}, [%4];"
                 : "=r"(r.x), "=r"(r.y), "=r"(r.z), "=r"(r.w) : "r"(addr));
    return r;
}

static __device__ __forceinline__ void mma_bf16(float* c, const Frag4& a,
                                                uint32_t b0, uint32_t b1) {
    asm volatile(
        "mma.sync.aligned.m16n8k16.row.col.f32.bf16.bf16.f32 "
        "{%0,%1,%2,%3}, {%4,%5,%6,%7}, {%8,%9}, {%0,%1,%2,%3};"
        : "+f"(c[0]), "+f"(c[1]), "+f"(c[2]), "+f"(c[3])
        : "r"(a.x), "r"(a.y), "r"(a.z), "r"(a.w), "r"(b0), "r"(b1));
}

__device__ __forceinline__ float gelu_exact(float x) {
    return 0.5f * x * (1.0f + erff(x * 0.70710678118654752f));
}

// ---------------------------------------------------------------------------
// HMMA GEMM: C[M,N] = (Ahi+Alo)[M,K] @ (Bhi+Blo)^T  (B stored [N,K], K-contig)
// 3-term split: AhiBhi + AhiBlo + AloBhi, fp32 accum.
// BM=128, BN in {128,256}, BK=32, 3-stage cp.async, 256 threads (8 warps 2x4),
// warptile 64 x (BN/4). Rows padded to 80B -> conflict-free ldmatrix.
// EPI: 0 = fp32 +bias ; 1 = gelu -> bf16 hi/lo ; 2 = fp32 +bias +residual
// ---------------------------------------------------------------------------
#define ROWB 80

template<int BN>
static __device__ __forceinline__ void load_stage(
    uint32_t st, const bf16* __restrict__ Ahi, const bf16* __restrict__ Alo,
    const bf16* __restrict__ Bhi, const bf16* __restrict__ Blo,
    int bm, int bn, int k0, int K, int tid)
{
    constexpr int TILE_A = 128 * ROWB;
    constexpr int OFF_BH = 2 * TILE_A;
    constexpr int OFF_BL = 2 * TILE_A + BN * ROWB;
#pragma unroll
    for (int i = 0; i < 2; i++) {            // A: 128 rows x 4 chunks = 512
        int c = tid + (i << 8);
        int r = c >> 2, q = c & 3;
        uint32_t so = (uint32_t)(r * ROWB + q * 16);
        size_t ga = (size_t)(bm + r) * K + k0 + (q << 3);
        cpa16(st + so, Ahi + ga);
        cpa16(st + TILE_A + so, Alo + ga);
    }
#pragma unroll
    for (int i = 0; i < BN / 64; i++) {      // B: BN rows x 4 chunks
        int c = tid + (i << 8);
        int r = c >> 2, q = c & 3;
        uint32_t so = (uint32_t)(r * ROWB + q * 16);
        size_t gb = (size_t)(bn + r) * K + k0 + (q << 3);
        cpa16(st + OFF_BH + so, Bhi + gb);
        cpa16(st + OFF_BL + so, Blo + gb);
    }
}

template<int EPI, int BN>
__global__ __launch_bounds__(256, 1) void tgemm_kernel(
    const bf16* __restrict__ Ahi, const bf16* __restrict__ Alo,
    const bf16* __restrict__ Bhi, const bf16* __restrict__ Blo,
    const float* __restrict__ bias, const float* __restrict__ res,
    float* __restrict__ Cf, bf16* __restrict__ Chi, bf16* __restrict__ Clo,
    int N, int K)
{
    constexpr int NT = BN / 32;          // n-tiles (8 wide) per warp
    constexpr int NP = NT / 2;           // ldmatrix groups (16 cols each)
    constexpr int TILE_A = 128 * ROWB;
    constexpr int TILE_B = BN * ROWB;
    constexpr int OFF_AL = TILE_A;
    constexpr int OFF_BH = 2 * TILE_A;
    constexpr int OFF_BL = 2 * TILE_A + TILE_B;
    constexpr int STAGE  = 2 * TILE_A + 2 * TILE_B;
    constexpr int WTN    = BN / 4;       // warptile n-width

    extern __shared__ __align__(1024) unsigned char smem[];
    uint32_t sb = smem_u32(smem);
    int tid = threadIdx.x, wid = tid >> 5, lane = tid & 31;
    int bm = blockIdx.x * 128, bn = blockIdx.y * BN;
    int wm = wid & 1, wn = wid >> 1;

    uint32_t a_lane = (uint32_t)((wm * 64 + (lane & 15)) * ROWB + ((lane >> 4) << 4));
    uint32_t b_lane = (uint32_t)(((lane & 7) + ((lane >> 4) << 3)) * ROWB
                                 + (((lane >> 3) & 1) << 4));

    float acc[4][NT][4];
#pragma unroll
    for (int i = 0; i < 4; i++)
#pragma unroll
        for (int j = 0; j < NT; j++)
#pragma unroll
            for (int e = 0; e < 4; e++) acc[i][j][e] = 0.f;

    int nk = K >> 5;
    load_stage<BN>(sb,         Ahi, Alo, Bhi, Blo, bm, bn, 0,  K, tid); CP_COMMIT();
    load_stage<BN>(sb + STAGE, Ahi, Alo, Bhi, Blo, bm, bn, 32, K, tid); CP_COMMIT();

    uint32_t stg[3] = {sb, sb + STAGE, sb + 2 * STAGE};
    int cur = 0, nxt = 2;
    for (int kt = 0; kt < nk; kt++) {
        CP_WAIT1();
        __syncthreads();

        int kf = kt + 2;
        if (kf < nk)
            load_stage<BN>(stg[nxt], Ahi, Alo, Bhi, Blo, bm, bn, kf << 5, K, tid);
        CP_COMMIT();

        uint32_t st = stg[cur];
        cur = (cur + 1) % 3; nxt = (nxt + 1) % 3;
#pragma unroll
        for (int ks = 0; ks < 2; ks++) {
            uint32_t kb = ks << 5;
            Frag4 ah[4], al[4];
#pragma unroll
            for (int mt = 0; mt < 4; mt++) {
                uint32_t ao = st + a_lane + mt * (16 * ROWB) + kb;
                ah[mt] = ldsm_x4(ao);
                al[mt] = ldsm_x4(ao + OFF_AL);
            }
#pragma unroll
            for (int np = 0; np < NP; np++) {
                uint32_t bo = st + b_lane + (wn * WTN + np * 16) * ROWB + kb;
                Frag4 bh = ldsm_x4(bo + OFF_BH);
                Frag4 bl = ldsm_x4(bo + OFF_BL);
#pragma unroll
                for (int mt = 0; mt < 4; mt++) {
                    mma_bf16(acc[mt][np * 2],     ah[mt], bh.x, bh.y);
                    mma_bf16(acc[mt][np * 2],     ah[mt], bl.x, bl.y);
                    mma_bf16(acc[mt][np * 2],     al[mt], bh.x, bh.y);
                    mma_bf16(acc[mt][np * 2 + 1], ah[mt], bh.z, bh.w);
                    mma_bf16(acc[mt][np * 2 + 1], ah[mt], bl.z, bl.w);
                    mma_bf16(acc[mt][np * 2 + 1], al[mt], bh.z, bh.w);
                }
            }
        }
    }
    __syncthreads();

    // Epilogue (register -> global)
    int row_in = lane >> 2;
    int col2   = (lane & 3) << 1;
#pragma unroll
    for (int mt = 0; mt < 4; mt++) {
#pragma unroll
        for (int nt = 0; nt < NT; nt++) {
            int col = bn + wn * WTN + nt * 8 + col2;
            float bx = bias[col], by = bias[col + 1];
#pragma unroll
            for (int half = 0; half < 2; half++) {
                int row = bm + wm * 64 + mt * 16 + row_in + half * 8;
                size_t off = (size_t)row * N + col;
                float v0 = acc[mt][nt][half * 2 + 0] + bx;
                float v1 = acc[mt][nt][half * 2 + 1] + by;
                if (EPI == 0) {
                    *(float2*)&Cf[off] = make_float2(v0, v1);
                } else if (EPI == 1) {
                    float g0 = gelu_exact(v0), g1 = gelu_exact(v1);
                    bf16 h0 = __float2bfloat16(g0), h1 = __float2bfloat16(g1);
                    __nv_bfloat162 hh; hh.x = h0; hh.y = h1;
                    __nv_bfloat162 ll;
                    ll.x = __float2bfloat16(g0 - __bfloat162float(h0));
                    ll.y = __float2bfloat16(g1 - __bfloat162float(h1));
                    *(__nv_bfloat162*)&Chi[off] = hh;
                    *(__nv_bfloat162*)&Clo[off] = ll;
                } else {
                    float2 rv = *(const float2*)&res[off];
                    *(float2*)&Cf[off] = make_float2(v0 + rv.x, v1 + rv.y);
                }
            }
        }
    }
}

#define SMEM256 (3 * (2 * 128 * ROWB + 2 * 256 * ROWB))   // 184320
#define SMEM128 (3 * (2 * 128 * ROWB + 2 * 128 * ROWB))   // 122880

// ---------------------------------------------------------------------------
// Weight transpose + bf16 hi/lo split: W[K,N] (N contig) -> T[N,K] (K contig)
// ---------------------------------------------------------------------------
__global__ void wconv_kernel(const float* __restrict__ W,
                             bf16* __restrict__ Th, bf16* __restrict__ Tl,
                             int K, int N, size_t inLs, size_t outLs)
{
    __shared__ float t[32][33];
    const float* Wl = W + blockIdx.z * inLs;
    Th += blockIdx.z * outLs;
    Tl += blockIdx.z * outLs;
    int n0 = blockIdx.x * 32, k0 = blockIdx.y * 32;
    int tx = threadIdx.x, ty = threadIdx.y;
#pragma unroll
    for (int i = 0; i < 4; i++)
        t[ty + 8 * i][tx] = Wl[(size_t)(k0 + ty + 8 * i) * N + n0 + tx];
    __syncthreads();
#pragma unroll
    for (int i = 0; i < 4; i++) {
        int n = ty + 8 * i;
        float v = t[tx][n];
        bf16 hv = __float2bfloat16(v);
        size_t o = (size_t)(n0 + n) * K + k0 + tx;
        Th[o] = hv;
        Tl[o] = __float2bfloat16(v - __bfloat162float(hv));
    }
}

// Pack per-layer QKV biases into [L, 3E]
__global__ void bpack_kernel(const float* __restrict__ bq, const float* __restrict__ bk,
                             const float* __restrict__ bv, float* __restrict__ out) {
    int i = blockIdx.x * 256 + threadIdx.x;
    int l = i / 3072, j = i % 3072;
    float v = (j < 1024) ? bq[l * 1024 + j]
            : (j < 2048) ? bk[l * 1024 + j - 1024]
                         : bv[l * 1024 + j - 2048];
    out[i] = v;
}

// ---------------------------------------------------------------------------
// Embedding
// ---------------------------------------------------------------------------
__global__ void embed_kernel(const int* __restrict__ x, const float* __restrict__ tok,
                             const float* __restrict__ pos, float* __restrict__ h) {
    int i = blockIdx.x * 256 + threadIdx.x;
    int row = i >> 10, e = i & 1023;
    int tkn = x[row];
    int t = row & (T_ - 1);
    h[i] = tok[(size_t)tkn * E_ + e] + pos[(size_t)t * E_ + e];
}

// ---------------------------------------------------------------------------
// LayerNorm -> bf16 hi/lo
// ---------------------------------------------------------------------------
__global__ __launch_bounds__(256) void ln_kernel(const float* __restrict__ in,
                                                 const float* __restrict__ gam,
                                                 const float* __restrict__ bet,
                                                 bf16* __restrict__ outhi,
                                                 bf16* __restrict__ outlo) {
    int row = blockIdx.x;
    const float* xr = in + (size_t)row * E_;
    float v0[4];
    float s = 0.f;
#pragma unroll
    for (int i = 0; i < 4; i++) { v0[i] = xr[threadIdx.x + 256 * i]; s += v0[i]; }

    __shared__ float sh[8];
    float t = s;
#pragma unroll
    for (int o = 16; o > 0; o >>= 1) t += __shfl_xor_sync(0xffffffffu, t, o);
    if ((threadIdx.x & 31) == 0) sh[threadIdx.x >> 5] = t;
    __syncthreads();
    float tot = 0.f;
#pragma unroll
    for (int i = 0; i < 8; i++) tot += sh[i];
    float mean = tot * (1.0f / E_);

    float vs = 0.f;
#pragma unroll
    for (int i = 0; i < 4; i++) { float d = v0[i] - mean; vs += d * d; }
    __syncthreads();
    t = vs;
#pragma unroll
    for (int o = 16; o > 0; o >>= 1) t += __shfl_xor_sync(0xffffffffu, t, o);
    if ((threadIdx.x & 31) == 0) sh[threadIdx.x >> 5] = t;
    __syncthreads();
    tot = 0.f;
#pragma unroll
    for (int i = 0; i < 8; i++) tot += sh[i];
    float rstd = rsqrtf(tot * (1.0f / E_) + 1e-5f);

#pragma unroll
    for (int i = 0; i < 4; i++) {
        int e = threadIdx.x + 256 * i;
        float y = (v0[i] - mean) * rstd * gam[e] + bet[e];
        bf16 hv = __float2bfloat16(y);
        size_t o = (size_t)row * E_ + e;
        outhi[o] = hv;
        outlo[o] = __float2bfloat16(y - __bfloat162float(hv));
    }
}

// ---------------------------------------------------------------------------
// Causal flash attention, fp32. qkv packed [M, 3E]; out -> bf16 hi/lo [M, E]
// ---------------------------------------------------------------------------
__global__ __launch_bounds__(64) void attn_kernel(const float* __restrict__ qkv,
                                                  bf16* __restrict__ ohi,
                                                  bf16* __restrict__ olo) {
    __shared__ float Ks[32][64];
    __shared__ float Vs[32][64];

    int qt = blockIdx.x & 31;
    int bh = blockIdx.x >> 5;
    int b  = bh >> 4;
    int hh = bh & 15;
    int row = qt * 64 + threadIdx.x;

    const float scale = 0.125f;
    float qr[64];
    const float* qp = qkv + (size_t)(b * T_ + row) * 3072 + hh * 64;
#pragma unroll
    for (int d = 0; d < 64; d++) qr[d] = qp[d] * scale;

    float acc[64];
#pragma unroll
    for (int d = 0; d < 64; d++) acc[d] = 0.f;
    float m = -1e30f, l = 0.f;

    int nt = qt * 2 + 2;
    for (int kt = 0; kt < nt; kt++) {
        int kb = kt * 32;
        {
            int tt = threadIdx.x;
#pragma unroll
            for (int i = 0; i < 8; i++) {
                int idx = (i * 64 + tt) * 4;
                int r = idx >> 6, c = idx & 63;
                size_t base = (size_t)(b * T_ + kb + r) * 3072 + hh * 64 + c;
                *(float4*)&Ks[r][c] = *(const float4*)(qkv + base + 1024);
                *(float4*)&Vs[r][c] = *(const float4*)(qkv + base + 2048);
            }
        }
        __syncthreads();

        float sv[32];
        float tmax = -1e30f;
#pragma unroll
        for (int c = 0; c < 32; c++) {
            if (kb + c <= row) {
                float sc = 0.f;
#pragma unroll
                for (int d = 0; d < 64; d += 4) {
                    float4 kv = *(const float4*)&Ks[c][d];
                    sc += qr[d] * kv.x + qr[d+1] * kv.y + qr[d+2] * kv.z + qr[d+3] * kv.w;
                }
                sv[c] = sc;
                tmax = fmaxf(tmax, sc);
            } else sv[c] = -1e30f;
        }
        float mnew = fmaxf(m, tmax);
        float corr = __expf(m - mnew);
        l *= corr;
#pragma unroll
        for (int d = 0; d < 64; d++) acc[d] *= corr;
#pragma unroll
        for (int c = 0; c < 32; c++) {
            float p = (kb + c <= row) ? __expf(sv[c] - mnew) : 0.f;
            l += p;
#pragma unroll
            for (int d = 0; d < 64; d += 4) {
                float4 vv = *(const float4*)&Vs[c][d];
                acc[d]   += p * vv.x;  acc[d+1] += p * vv.y;
                acc[d+2] += p * vv.z;  acc[d+3] += p * vv.w;
            }
        }
        m = mnew;
        __syncthreads();
    }

    float inv = 1.0f / l;
    size_t ob = (size_t)(b * T_ + row) * E_ + hh * 64;
#pragma unroll
    for (int d = 0; d < 64; d++) {
        float y = acc[d] * inv;
        bf16 hv = __float2bfloat16(y);
        ohi[ob + d] = hv;
        olo[ob + d] = __float2bfloat16(y - __bfloat162float(hv));
    }
}

// ---------------------------------------------------------------------------
// Host orchestration
// ---------------------------------------------------------------------------
extern "C" void kernel_launch(void* const* d_in, const int* in_sizes, int n_in,
                              void* d_out, int out_size) {
    const int*   x    = (const int*)  d_in[0];
    const float* tok  = (const float*)d_in[1];
    const float* pos  = (const float*)d_in[2];
    const float* Wq   = (const float*)d_in[3];
    const float* bq   = (const float*)d_in[4];
    const float* Wk   = (const float*)d_in[5];
    const float* bk   = (const float*)d_in[6];
    const float* Wv   = (const float*)d_in[7];
    const float* bv   = (const float*)d_in[8];
    const float* Wo   = (const float*)d_in[9];
    const float* bo   = (const float*)d_in[10];
    const float* ln1g = (const float*)d_in[11];
    const float* ln1b = (const float*)d_in[12];
    const float* W1   = (const float*)d_in[13];
    const float* b1   = (const float*)d_in[14];
    const float* W2   = (const float*)d_in[15];
    const float* b2   = (const float*)d_in[16];
    const float* ln2g = (const float*)d_in[17];
    const float* ln2b = (const float*)d_in[18];
    const float* lnfg = (const float*)d_in[19];
    const float* lnfb = (const float*)d_in[20];
    const float* Wout = (const float*)d_in[21];
    const float* bout = (const float*)d_in[22];
    float* out = (float*)d_out;

    float *h, *qkv, *bqkv;
    bf16 *xnh, *xnl, *oh, *ol, *mph, *mpl;
    bf16 *qkvTh, *qkvTl, *woTh, *woTl, *w1Th, *w1Tl, *w2Th, *w2Tl, *wouTh, *wouTl;
    cudaGetSymbolAddress((void**)&h,    g_h);
    cudaGetSymbolAddress((void**)&qkv,  g_qkv);
    cudaGetSymbolAddress((void**)&bqkv, g_bqkv);
    cudaGetSymbolAddress((void**)&xnh,  g_xn_hi);  cudaGetSymbolAddress((void**)&xnl, g_xn_lo);
    cudaGetSymbolAddress((void**)&oh,   g_o_hi);   cudaGetSymbolAddress((void**)&ol,  g_o_lo);
    cudaGetSymbolAddress((void**)&mph,  g_mlp_hi); cudaGetSymbolAddress((void**)&mpl, g_mlp_lo);
    cudaGetSymbolAddress((void**)&qkvTh, g_qkvT_hi); cudaGetSymbolAddress((void**)&qkvTl, g_qkvT_lo);
    cudaGetSymbolAddress((void**)&woTh,  g_woT_hi);  cudaGetSymbolAddress((void**)&woTl,  g_woT_lo);
    cudaGetSymbolAddress((void**)&w1Th,  g_w1T_hi);  cudaGetSymbolAddress((void**)&w1Tl,  g_w1T_lo);
    cudaGetSymbolAddress((void**)&w2Th,  g_w2T_hi);  cudaGetSymbolAddress((void**)&w2Tl,  g_w2T_lo);
    cudaGetSymbolAddress((void**)&wouTh, g_woutT_hi); cudaGetSymbolAddress((void**)&wouTl, g_woutT_lo);

    cudaFuncSetAttribute((const void*)tgemm_kernel<0, 256>, cudaFuncAttributeMaxDynamicSharedMemorySize, SMEM256);
    cudaFuncSetAttribute((const void*)tgemm_kernel<1, 256>, cudaFuncAttributeMaxDynamicSharedMemorySize, SMEM256);
    cudaFuncSetAttribute((const void*)tgemm_kernel<2, 128>, cudaFuncAttributeMaxDynamicSharedMemorySize, SMEM128);

    const size_t EE = (size_t)E_ * E_, EF = (size_t)E_ * F_;
    dim3 tb(32, 8);
    wconv_kernel<<<dim3(32, 32, L_), tb>>>(Wq, qkvTh,          qkvTl,          E_, E_, EE, 3 * EE);
    wconv_kernel<<<dim3(32, 32, L_), tb>>>(Wk, qkvTh + EE,     qkvTl + EE,     E_, E_, EE, 3 * EE);
    wconv_kernel<<<dim3(32, 32, L_), tb>>>(Wv, qkvTh + 2 * EE, qkvTl + 2 * EE, E_, E_, EE, 3 * EE);
    wconv_kernel<<<dim3(32, 32, L_), tb>>>(Wo, woTh, woTl, E_, E_, EE, EE);
    wconv_kernel<<<dim3(128, 32, L_), tb>>>(W1, w1Th, w1Tl, E_, F_, EF, EF);
    wconv_kernel<<<dim3(32, 128, L_), tb>>>(W2, w2Th, w2Tl, F_, E_, EF, EF);
    wconv_kernel<<<dim3(1000, 32, 1), tb>>>(Wout, wouTh, wouTl, E_, V_, 0, 0);
    bpack_kernel<<<(L_ * 3 * E_) / 256, 256>>>(bq, bk, bv, bqkv);

    embed_kernel<<<(M_ * E_) / 256, 256>>>(x, tok, pos, h);

    for (int l = 0; l < L_; l++) {
        ln_kernel<<<M_, 256>>>(h, ln1g + l * E_, ln1b + l * E_, xnh, xnl);
        tgemm_kernel<0, 256><<<dim3(M_ / 128, 12), 256, SMEM256>>>(
            xnh, xnl, qkvTh + l * 3 * EE, qkvTl + l * 3 * EE,
            bqkv + l * 3 * E_, nullptr, qkv, nullptr, nullptr, 3 * E_, E_);
        attn_kernel<<<B_ * H_ * (T_ / 64), 64>>>(qkv, oh, ol);
        tgemm_kernel<2, 128><<<dim3(M_ / 128, 8), 256, SMEM128>>>(
            oh, ol, woTh + l * EE, woTl + l * EE,
            bo + l * E_, h, h, nullptr, nullptr, E_, E_);
        ln_kernel<<<M_, 256>>>(h, ln2g + l * E_, ln2b + l * E_, xnh, xnl);
        tgemm_kernel<1, 256><<<dim3(M_ / 128, 16), 256, SMEM256>>>(
            xnh, xnl, w1Th + l * EF, w1Tl + l * EF,
            b1 + l * F_, nullptr, nullptr, mph, mpl, F_, E_);
        tgemm_kernel<2, 128><<<dim3(M_ / 128, 8), 256, SMEM128>>>(
            mph, mpl, w2Th + l * EF, w2Tl + l * EF,
            b2 + l * E_, h, h, nullptr, nullptr, E_, F_);
    }

    ln_kernel<<<M_, 256>>>(h, lnfg, lnfb, xnh, xnl);
    tgemm_kernel<0, 256><<<dim3(M_ / 128, V_ / 256), 256, SMEM256>>>(
        xnh, xnl, wouTh, wouTl, bout, nullptr, out, nullptr, nullptr, V_, E_);
}

// round 5
// speedup vs baseline: 1.8668x; 1.1660x over previous
#include <cuda_runtime.h>
#include <cuda_fp16.h>
#include <math.h>
#include <stdint.h>

// Problem dims
#define V_ 32000
#define E_ 1024
#define H_ 16
#define F_ 4096
#define L_ 4
#define T_ 2048
#define B_ 2
#define D_ 64
#define M_ (B_*T_)   // 4096

// ---------------------------------------------------------------------------
// Scratch (device globals; allocation APIs are forbidden)
// ---------------------------------------------------------------------------
__device__ float g_h  [M_*E_];
__device__ float g_qkv[M_*3*E_];
__device__ float g_bqkv[L_*3*E_];
__device__ __half g_xn [M_*E_];
__device__ __half g_o  [M_*E_];
__device__ __half g_mlp[M_*F_];
__device__ __half g_qkvT_hi[L_*3*E_*E_], g_qkvT_lo[L_*3*E_*E_];
__device__ __half g_woT_hi [L_*E_*E_],   g_woT_lo [L_*E_*E_];
__device__ __half g_w1T_hi [L_*F_*E_],   g_w1T_lo [L_*F_*E_];
__device__ __half g_w2T_hi [L_*E_*F_],   g_w2T_lo [L_*E_*F_];
__device__ __half g_woutT_hi[(size_t)V_*E_], g_woutT_lo[(size_t)V_*E_];

// ---------------------------------------------------------------------------
// PTX helpers
// ---------------------------------------------------------------------------
__device__ __forceinline__ uint32_t smem_u32(const void* p) {
    uint32_t a;
    asm("{ .reg .u64 t; cvta.to.shared.u64 t, %1; cvt.u32.u64 %0, t; }" : "=r"(a) : "l"(p));
    return a;
}
static __device__ __forceinline__ void cpa16(uint32_t s, const void* g) {
    asm volatile("cp.async.cg.shared.global [%0], [%1], 16;" :: "r"(s), "l"(g) : "memory");
}
#define CP_COMMIT() asm volatile("cp.async.commit_group;" ::: "memory")
#define CP_WAIT1()  asm volatile("cp.async.wait_group 1;" ::: "memory")

struct Frag4 { uint32_t x, y, z, w; };

static __device__ __forceinline__ Frag4 ldsm_x4(uint32_t addr) {
    Frag4 r;
    asm volatile("ldmatrix.sync.aligned.m8n8.x4.shared.b16 {%0,%1,%2,%3}, [%4];"
                 : "=r"(r.x), "=r"(r.y), "=r"(r.z), "=r"(r.w) : "r"(addr));
    return r;
}

static __device__ __forceinline__ void mma_f16(float* c, const Frag4& a,
                                               uint32_t b0, uint32_t b1) {
    asm volatile(
        "mma.sync.aligned.m16n8k16.row.col.f32.f16.f16.f32 "
        "{%0,%1,%2,%3}, {%4,%5,%6,%7}, {%8,%9}, {%0,%1,%2,%3};"
        : "+f"(c[0]), "+f"(c[1]), "+f"(c[2]), "+f"(c[3])
        : "r"(a.x), "r"(a.y), "r"(a.z), "r"(a.w), "r"(b0), "r"(b1));
}

__device__ __forceinline__ float gelu_exact(float x) {
    return 0.5f * x * (1.0f + erff(x * 0.70710678118654752f));
}

// ---------------------------------------------------------------------------
// HMMA GEMM: C[M,N] = A[M,K] @ (Bhi+Blo)^T   (B stored [N,K], K-contig, fp16)
// 2-term: A*Bhi + A*Blo, fp32 accum. A single fp16 (activations),
// B split fp16 pair (weights, precomputed -> representation error 2^-22).
// BM=128, BN in {128,256}, BK=32, 3-stage cp.async, 256 threads (8 warps 2x4),
// warptile 64 x (BN/4). Rows padded to 80B -> conflict-free ldmatrix.
// EPI: 0 = fp32 +bias ; 1 = gelu -> fp16 ; 2 = fp32 +bias +residual
// ---------------------------------------------------------------------------
#define ROWB 80

template<int BN>
static __device__ __forceinline__ void load_stage(
    uint32_t st, const __half* __restrict__ A,
    const __half* __restrict__ Bhi, const __half* __restrict__ Blo,
    int bm, int bn, int k0, int K, int tid)
{
    constexpr int TILE_A = 128 * ROWB;
    constexpr int OFF_BH = TILE_A;
    constexpr int OFF_BL = TILE_A + BN * ROWB;
#pragma unroll
    for (int i = 0; i < 2; i++) {            // A: 128 rows x 4 chunks = 512
        int c = tid + (i << 8);
        int r = c >> 2, q = c & 3;
        uint32_t so = (uint32_t)(r * ROWB + q * 16);
        size_t ga = (size_t)(bm + r) * K + k0 + (q << 3);
        cpa16(st + so, A + ga);
    }
#pragma unroll
    for (int i = 0; i < BN / 64; i++) {      // B: BN rows x 4 chunks
        int c = tid + (i << 8);
        int r = c >> 2, q = c & 3;
        uint32_t so = (uint32_t)(r * ROWB + q * 16);
        size_t gb = (size_t)(bn + r) * K + k0 + (q << 3);
        cpa16(st + OFF_BH + so, Bhi + gb);
        cpa16(st + OFF_BL + so, Blo + gb);
    }
}

template<int EPI, int BN, int MINB>
__global__ __launch_bounds__(256, MINB) void tgemm_kernel(
    const __half* __restrict__ A,
    const __half* __restrict__ Bhi, const __half* __restrict__ Blo,
    const float* __restrict__ bias, const float* __restrict__ res,
    float* __restrict__ Cf, __half* __restrict__ Ch,
    int N, int K)
{
    constexpr int NT = BN / 32;          // n-tiles (8 wide) per warp
    constexpr int NP = NT / 2;           // ldmatrix groups (16 cols each)
    constexpr int TILE_A = 128 * ROWB;
    constexpr int TILE_B = BN * ROWB;
    constexpr int OFF_BH = TILE_A;
    constexpr int OFF_BL = TILE_A + TILE_B;
    constexpr int STAGE  = TILE_A + 2 * TILE_B;
    constexpr int WTN    = BN / 4;       // warptile n-width

    extern __shared__ __align__(1024) unsigned char smem[];
    uint32_t sb = smem_u32(smem);
    int tid = threadIdx.x, wid = tid >> 5, lane = tid & 31;
    int bm = blockIdx.x * 128, bn = blockIdx.y * BN;
    int wm = wid & 1, wn = wid >> 1;

    uint32_t a_lane = (uint32_t)((wm * 64 + (lane & 15)) * ROWB + ((lane >> 4) << 4));
    uint32_t b_lane = (uint32_t)(((lane & 7) + ((lane >> 4) << 3)) * ROWB
                                 + (((lane >> 3) & 1) << 4));

    float acc[4][NT][4];
#pragma unroll
    for (int i = 0; i < 4; i++)
#pragma unroll
        for (int j = 0; j < NT; j++)
#pragma unroll
            for (int e = 0; e < 4; e++) acc[i][j][e] = 0.f;

    int nk = K >> 5;
    load_stage<BN>(sb,         A, Bhi, Blo, bm, bn, 0,  K, tid); CP_COMMIT();
    load_stage<BN>(sb + STAGE, A, Bhi, Blo, bm, bn, 32, K, tid); CP_COMMIT();

    uint32_t stg[3] = {sb, sb + STAGE, sb + 2 * STAGE};
    int cur = 0, nxt = 2;
    for (int kt = 0; kt < nk; kt++) {
        CP_WAIT1();
        __syncthreads();

        int kf = kt + 2;
        if (kf < nk)
            load_stage<BN>(stg[nxt], A, Bhi, Blo, bm, bn, kf << 5, K, tid);
        CP_COMMIT();

        uint32_t st = stg[cur];
        cur = (cur + 1) % 3; nxt = (nxt + 1) % 3;
#pragma unroll
        for (int ks = 0; ks < 2; ks++) {
            uint32_t kb = ks << 5;
            Frag4 ah[4];
#pragma unroll
            for (int mt = 0; mt < 4; mt++)
                ah[mt] = ldsm_x4(st + a_lane + mt * (16 * ROWB) + kb);
#pragma unroll
            for (int np = 0; np < NP; np++) {
                uint32_t bo = st + b_lane + (wn * WTN + np * 16) * ROWB + kb;
                Frag4 bh = ldsm_x4(bo + OFF_BH);
                Frag4 bl = ldsm_x4(bo + OFF_BL);
#pragma unroll
                for (int mt = 0; mt < 4; mt++) {
                    mma_f16(acc[mt][np * 2],     ah[mt], bh.x, bh.y);
                    mma_f16(acc[mt][np * 2],     ah[mt], bl.x, bl.y);
                    mma_f16(acc[mt][np * 2 + 1], ah[mt], bh.z, bh.w);
                    mma_f16(acc[mt][np * 2 + 1], ah[mt], bl.z, bl.w);
                }
            }
        }
    }
    __syncthreads();

    // Epilogue (register -> global)
    int row_in = lane >> 2;
    int col2   = (lane & 3) << 1;
#pragma unroll
    for (int mt = 0; mt < 4; mt++) {
#pragma unroll
        for (int nt = 0; nt < NT; nt++) {
            int col = bn + wn * WTN + nt * 8 + col2;
            float bx = bias[col], by = bias[col + 1];
#pragma unroll
            for (int half = 0; half < 2; half++) {
                int row = bm + wm * 64 + mt * 16 + row_in + half * 8;
                size_t off = (size_t)row * N + col;
                float v0 = acc[mt][nt][half * 2 + 0] + bx;
                float v1 = acc[mt][nt][half * 2 + 1] + by;
                if (EPI == 0) {
                    *(float2*)&Cf[off] = make_float2(v0, v1);
                } else if (EPI == 1) {
                    __half2 hh;
                    hh.x = __float2half(gelu_exact(v0));
                    hh.y = __float2half(gelu_exact(v1));
                    *(__half2*)&Ch[off] = hh;
                } else {
                    float2 rv = *(const float2*)&res[off];
                    *(float2*)&Cf[off] = make_float2(v0 + rv.x, v1 + rv.y);
                }
            }
        }
    }
}

#define SMEM256 (3 * (128 * ROWB + 2 * 256 * ROWB))   // 153600
#define SMEM128 (3 * (128 * ROWB + 2 * 128 * ROWB))   // 92160

// ---------------------------------------------------------------------------
// Weight transpose + fp16 hi/lo split: W[K,N] (N contig) -> T[N,K] (K contig)
// ---------------------------------------------------------------------------
__global__ void wconv_kernel(const float* __restrict__ W,
                             __half* __restrict__ Th, __half* __restrict__ Tl,
                             int K, int N, size_t inLs, size_t outLs)
{
    __shared__ float t[32][33];
    const float* Wl = W + blockIdx.z * inLs;
    Th += blockIdx.z * outLs;
    Tl += blockIdx.z * outLs;
    int n0 = blockIdx.x * 32, k0 = blockIdx.y * 32;
    int tx = threadIdx.x, ty = threadIdx.y;
#pragma unroll
    for (int i = 0; i < 4; i++)
        t[ty + 8 * i][tx] = Wl[(size_t)(k0 + ty + 8 * i) * N + n0 + tx];
    __syncthreads();
#pragma unroll
    for (int i = 0; i < 4; i++) {
        int n = ty + 8 * i;
        float v = t[tx][n];
        __half hv = __float2half(v);
        size_t o = (size_t)(n0 + n) * K + k0 + tx;
        Th[o] = hv;
        Tl[o] = __float2half(v - __half2float(hv));
    }
}

// Pack per-layer QKV biases into [L, 3E]
__global__ void bpack_kernel(const float* __restrict__ bq, const float* __restrict__ bk,
                             const float* __restrict__ bv, float* __restrict__ out) {
    int i = blockIdx.x * 256 + threadIdx.x;
    int l = i / 3072, j = i % 3072;
    float v = (j < 1024) ? bq[l * 1024 + j]
            : (j < 2048) ? bk[l * 1024 + j - 1024]
                         : bv[l * 1024 + j - 2048];
    out[i] = v;
}

// ---------------------------------------------------------------------------
// Embedding
// ---------------------------------------------------------------------------
__global__ void embed_kernel(const int* __restrict__ x, const float* __restrict__ tok,
                             const float* __restrict__ pos, float* __restrict__ h) {
    int i = blockIdx.x * 256 + threadIdx.x;
    int row = i >> 10, e = i & 1023;
    int tkn = x[row];
    int t = row & (T_ - 1);
    h[i] = tok[(size_t)tkn * E_ + e] + pos[(size_t)t * E_ + e];
}

// ---------------------------------------------------------------------------
// LayerNorm -> fp16
// ---------------------------------------------------------------------------
__global__ __launch_bounds__(256) void ln_kernel(const float* __restrict__ in,
                                                 const float* __restrict__ gam,
                                                 const float* __restrict__ bet,
                                                 __half* __restrict__ outh) {
    int row = blockIdx.x;
    const float* xr = in + (size_t)row * E_;
    float v0[4];
    float s = 0.f;
#pragma unroll
    for (int i = 0; i < 4; i++) { v0[i] = xr[threadIdx.x + 256 * i]; s += v0[i]; }

    __shared__ float sh[8];
    float t = s;
#pragma unroll
    for (int o = 16; o > 0; o >>= 1) t += __shfl_xor_sync(0xffffffffu, t, o);
    if ((threadIdx.x & 31) == 0) sh[threadIdx.x >> 5] = t;
    __syncthreads();
    float tot = 0.f;
#pragma unroll
    for (int i = 0; i < 8; i++) tot += sh[i];
    float mean = tot * (1.0f / E_);

    float vs = 0.f;
#pragma unroll
    for (int i = 0; i < 4; i++) { float d = v0[i] - mean; vs += d * d; }
    __syncthreads();
    t = vs;
#pragma unroll
    for (int o = 16; o > 0; o >>= 1) t += __shfl_xor_sync(0xffffffffu, t, o);
    if ((threadIdx.x & 31) == 0) sh[threadIdx.x >> 5] = t;
    __syncthreads();
    tot = 0.f;
#pragma unroll
    for (int i = 0; i < 8; i++) tot += sh[i];
    float rstd = rsqrtf(tot * (1.0f / E_) + 1e-5f);

#pragma unroll
    for (int i = 0; i < 4; i++) {
        int e = threadIdx.x + 256 * i;
        float y = (v0[i] - mean) * rstd * gam[e] + bet[e];
        outh[(size_t)row * E_ + e] = __float2half(y);
    }
}

// ---------------------------------------------------------------------------
// Causal flash attention, fp32. qkv packed [M, 3E]; out -> fp16 [M, E]
// ---------------------------------------------------------------------------
__global__ __launch_bounds__(64) void attn_kernel(const float* __restrict__ qkv,
                                                  __half* __restrict__ oh) {
    __shared__ float Ks[32][64];
    __shared__ float Vs[32][64];

    int qt = blockIdx.x & 31;
    int bh = blockIdx.x >> 5;
    int b  = bh >> 4;
    int hh = bh & 15;
    int row = qt * 64 + threadIdx.x;

    const float scale = 0.125f;
    float qr[64];
    const float* qp = qkv + (size_t)(b * T_ + row) * 3072 + hh * 64;
#pragma unroll
    for (int d = 0; d < 64; d++) qr[d] = qp[d] * scale;

    float acc[64];
#pragma unroll
    for (int d = 0; d < 64; d++) acc[d] = 0.f;
    float m = -1e30f, l = 0.f;

    int nt = qt * 2 + 2;
    for (int kt = 0; kt < nt; kt++) {
        int kb = kt * 32;
        {
            int tt = threadIdx.x;
#pragma unroll
            for (int i = 0; i < 8; i++) {
                int idx = (i * 64 + tt) * 4;
                int r = idx >> 6, c = idx & 63;
                size_t base = (size_t)(b * T_ + kb + r) * 3072 + hh * 64 + c;
                *(float4*)&Ks[r][c] = *(const float4*)(qkv + base + 1024);
                *(float4*)&Vs[r][c] = *(const float4*)(qkv + base + 2048);
            }
        }
        __syncthreads();

        float sv[32];
        float tmax = -1e30f;
#pragma unroll
        for (int c = 0; c < 32; c++) {
            if (kb + c <= row) {
                float sc = 0.f;
#pragma unroll
                for (int d = 0; d < 64; d += 4) {
                    float4 kv = *(const float4*)&Ks[c][d];
                    sc += qr[d] * kv.x + qr[d+1] * kv.y + qr[d+2] * kv.z + qr[d+3] * kv.w;
                }
                sv[c] = sc;
                tmax = fmaxf(tmax, sc);
            } else sv[c] = -1e30f;
        }
        float mnew = fmaxf(m, tmax);
        float corr = __expf(m - mnew);
        l *= corr;
#pragma unroll
        for (int d = 0; d < 64; d++) acc[d] *= corr;
#pragma unroll
        for (int c = 0; c < 32; c++) {
            float p = (kb + c <= row) ? __expf(sv[c] - mnew) : 0.f;
            l += p;
#pragma unroll
            for (int d = 0; d < 64; d += 4) {
                float4 vv = *(const float4*)&Vs[c][d];
                acc[d]   += p * vv.x;  acc[d+1] += p * vv.y;
                acc[d+2] += p * vv.z;  acc[d+3] += p * vv.w;
            }
        }
        m = mnew;
        __syncthreads();
    }

    float inv = 1.0f / l;
    size_t ob = (size_t)(b * T_ + row) * E_ + hh * 64;
#pragma unroll
    for (int d = 0; d < 64; d++)
        oh[ob + d] = __float2half(acc[d] * inv);
}

// ---------------------------------------------------------------------------
// Host orchestration
// ---------------------------------------------------------------------------
extern "C" void kernel_launch(void* const* d_in, const int* in_sizes, int n_in,
                              void* d_out, int out_size) {
    const int*   x    = (const int*)  d_in[0];
    const float* tok  = (const float*)d_in[1];
    const float* pos  = (const float*)d_in[2];
    const float* Wq   = (const float*)d_in[3];
    const float* bq   = (const float*)d_in[4];
    const float* Wk   = (const float*)d_in[5];
    const float* bk   = (const float*)d_in[6];
    const float* Wv   = (const float*)d_in[7];
    const float* bv   = (const float*)d_in[8];
    const float* Wo   = (const float*)d_in[9];
    const float* bo   = (const float*)d_in[10];
    const float* ln1g = (const float*)d_in[11];
    const float* ln1b = (const float*)d_in[12];
    const float* W1   = (const float*)d_in[13];
    const float* b1   = (const float*)d_in[14];
    const float* W2   = (const float*)d_in[15];
    const float* b2   = (const float*)d_in[16];
    const float* ln2g = (const float*)d_in[17];
    const float* ln2b = (const float*)d_in[18];
    const float* lnfg = (const float*)d_in[19];
    const float* lnfb = (const float*)d_in[20];
    const float* Wout = (const float*)d_in[21];
    const float* bout = (const float*)d_in[22];
    float* out = (float*)d_out;

    float *h, *qkv, *bqkv;
    __half *xn, *o, *mlp;
    __half *qkvTh, *qkvTl, *woTh, *woTl, *w1Th, *w1Tl, *w2Th, *w2Tl, *wouTh, *wouTl;
    cudaGetSymbolAddress((void**)&h,    g_h);
    cudaGetSymbolAddress((void**)&qkv,  g_qkv);
    cudaGetSymbolAddress((void**)&bqkv, g_bqkv);
    cudaGetSymbolAddress((void**)&xn,   g_xn);
    cudaGetSymbolAddress((void**)&o,    g_o);
    cudaGetSymbolAddress((void**)&mlp,  g_mlp);
    cudaGetSymbolAddress((void**)&qkvTh, g_qkvT_hi); cudaGetSymbolAddress((void**)&qkvTl, g_qkvT_lo);
    cudaGetSymbolAddress((void**)&woTh,  g_woT_hi);  cudaGetSymbolAddress((void**)&woTl,  g_woT_lo);
    cudaGetSymbolAddress((void**)&w1Th,  g_w1T_hi);  cudaGetSymbolAddress((void**)&w1Tl,  g_w1T_lo);
    cudaGetSymbolAddress((void**)&w2Th,  g_w2T_hi);  cudaGetSymbolAddress((void**)&w2Tl,  g_w2T_lo);
    cudaGetSymbolAddress((void**)&wouTh, g_woutT_hi); cudaGetSymbolAddress((void**)&wouTl, g_woutT_lo);

    cudaFuncSetAttribute((const void*)tgemm_kernel<0, 256, 1>, cudaFuncAttributeMaxDynamicSharedMemorySize, SMEM256);
    cudaFuncSetAttribute((const void*)tgemm_kernel<1, 256, 1>, cudaFuncAttributeMaxDynamicSharedMemorySize, SMEM256);
    cudaFuncSetAttribute((const void*)tgemm_kernel<2, 128, 2>, cudaFuncAttributeMaxDynamicSharedMemorySize, SMEM128);

    const size_t EE = (size_t)E_ * E_, EF = (size_t)E_ * F_;
    dim3 tb(32, 8);
    wconv_kernel<<<dim3(32, 32, L_), tb>>>(Wq, qkvTh,          qkvTl,          E_, E_, EE, 3 * EE);
    wconv_kernel<<<dim3(32, 32, L_), tb>>>(Wk, qkvTh + EE,     qkvTl + EE,     E_, E_, EE, 3 * EE);
    wconv_kernel<<<dim3(32, 32, L_), tb>>>(Wv, qkvTh + 2 * EE, qkvTl + 2 * EE, E_, E_, EE, 3 * EE);
    wconv_kernel<<<dim3(32, 32, L_), tb>>>(Wo, woTh, woTl, E_, E_, EE, EE);
    wconv_kernel<<<dim3(128, 32, L_), tb>>>(W1, w1Th, w1Tl, E_, F_, EF, EF);
    wconv_kernel<<<dim3(32, 128, L_), tb>>>(W2, w2Th, w2Tl, F_, E_, EF, EF);
    wconv_kernel<<<dim3(1000, 32, 1), tb>>>(Wout, wouTh, wouTl, E_, V_, 0, 0);
    bpack_kernel<<<(L_ * 3 * E_) / 256, 256>>>(bq, bk, bv, bqkv);

    embed_kernel<<<(M_ * E_) / 256, 256>>>(x, tok, pos, h);

    for (int l = 0; l < L_; l++) {
        ln_kernel<<<M_, 256>>>(h, ln1g + l * E_, ln1b + l * E_, xn);
        tgemm_kernel<0, 256, 1><<<dim3(M_ / 128, 12), 256, SMEM256>>>(
            xn, qkvTh + l * 3 * EE, qkvTl + l * 3 * EE,
            bqkv + l * 3 * E_, nullptr, qkv, nullptr, 3 * E_, E_);
        attn_kernel<<<B_ * H_ * (T_ / 64), 64>>>(qkv, o);
        tgemm_kernel<2, 128, 2><<<dim3(M_ / 128, 8), 256, SMEM128>>>(
            o, woTh + l * EE, woTl + l * EE,
            bo + l * E_, h, h, nullptr, E_, E_);
        ln_kernel<<<M_, 256>>>(h, ln2g + l * E_, ln2b + l * E_, xn);
        tgemm_kernel<1, 256, 1><<<dim3(M_ / 128, 16), 256, SMEM256>>>(
            xn, w1Th + l * EF, w1Tl + l * EF,
            b1 + l * F_, nullptr, nullptr, mlp, F_, E_);
        tgemm_kernel<2, 128, 2><<<dim3(M_ / 128, 8), 256, SMEM128>>>(
            mlp, w2Th + l * EF, w2Tl + l * EF,
            b2 + l * E_, h, h, nullptr, E_, F_);
    }

    ln_kernel<<<M_, 256>>>(h, lnfg, lnfb, xn);
    tgemm_kernel<0, 256, 1><<<dim3(M_ / 128, V_ / 256), 256, SMEM256>>>(
        xn, wouTh, wouTl, bout, nullptr, out, nullptr, V_, E_);
}

// round 6
// speedup vs baseline: 2.2426x; 1.2013x over previous
#include <cuda_runtime.h>
#include <cuda_fp16.h>
#include <math.h>
#include <stdint.h>

// Problem dims
#define V_ 32000
#define E_ 1024
#define H_ 16
#define F_ 4096
#define L_ 4
#define T_ 2048
#define B_ 2
#define D_ 64
#define M_ (B_*T_)   // 4096

// ---------------------------------------------------------------------------
// Scratch (device globals; allocation APIs are forbidden)
// ---------------------------------------------------------------------------
__device__ float g_h  [M_*E_];
__device__ float g_qkv[M_*3*E_];
__device__ float g_bqkv[L_*3*E_];
__device__ __half g_xn [M_*E_];
__device__ __half g_o  [M_*E_];
__device__ __half g_mlp[M_*F_];
__device__ __half g_qkvT[L_*3*E_*E_];
__device__ __half g_woT [L_*E_*E_];
__device__ __half g_w1T [L_*F_*E_];
__device__ __half g_w2T [L_*E_*F_];
__device__ __half g_woutT[(size_t)V_*E_];

// ---------------------------------------------------------------------------
// PTX helpers
// ---------------------------------------------------------------------------
__device__ __forceinline__ uint32_t smem_u32(const void* p) {
    uint32_t a;
    asm("{ .reg .u64 t; cvta.to.shared.u64 t, %1; cvt.u32.u64 %0, t; }" : "=r"(a) : "l"(p));
    return a;
}
static __device__ __forceinline__ void cpa16(uint32_t s, const void* g) {
    asm volatile("cp.async.cg.shared.global [%0], [%1], 16;" :: "r"(s), "l"(g) : "memory");
}
#define CP_COMMIT() asm volatile("cp.async.commit_group;" ::: "memory")
#define CP_WAIT1()  asm volatile("cp.async.wait_group 1;" ::: "memory")

struct Frag4 { uint32_t x, y, z, w; };

static __device__ __forceinline__ Frag4 ldsm_x4(uint32_t addr) {
    Frag4 r;
    asm volatile("ldmatrix.sync.aligned.m8n8.x4.shared.b16 {%0,%1,%2,%3}, [%4];"
                 : "=r"(r.x), "=r"(r.y), "=r"(r.z), "=r"(r.w) : "r"(addr));
    return r;
}

static __device__ __forceinline__ void mma_f16(float* c, const Frag4& a,
                                               uint32_t b0, uint32_t b1) {
    asm volatile(
        "mma.sync.aligned.m16n8k16.row.col.f32.f16.f16.f32 "
        "{%0,%1,%2,%3}, {%4,%5,%6,%7}, {%8,%9}, {%0,%1,%2,%3};"
        : "+f"(c[0]), "+f"(c[1]), "+f"(c[2]), "+f"(c[3])
        : "r"(a.x), "r"(a.y), "r"(a.z), "r"(a.w), "r"(b0), "r"(b1));
}

__device__ __forceinline__ float gelu_exact(float x) {
    return 0.5f * x * (1.0f + erff(x * 0.70710678118654752f));
}

// ---------------------------------------------------------------------------
// HMMA GEMM: C[M,N] = A[M,K] @ B^T   (A, B fp16; B stored [N,K], K-contig)
// Single-term fp16 MMA, fp32 accum.
// BM=128, BN in {128,256}, BK=32, 3-stage cp.async, 256 threads (8 warps 2x4),
// warptile 64 x (BN/4). Rows padded to 80B -> conflict-free ldmatrix.
// EPI: 0 = fp32 +bias ; 1 = gelu -> fp16 ; 2 = fp32 +bias +residual
// ---------------------------------------------------------------------------
#define ROWB 80

template<int BN>
static __device__ __forceinline__ void load_stage(
    uint32_t st, const __half* __restrict__ A, const __half* __restrict__ Bm,
    int bm, int bn, int k0, int K, int tid)
{
    constexpr int TILE_A = 128 * ROWB;
#pragma unroll
    for (int i = 0; i < 2; i++) {            // A: 128 rows x 4 chunks = 512
        int c = tid + (i << 8);
        int r = c >> 2, q = c & 3;
        uint32_t so = (uint32_t)(r * ROWB + q * 16);
        cpa16(st + so, A + (size_t)(bm + r) * K + k0 + (q << 3));
    }
#pragma unroll
    for (int i = 0; i < BN / 64; i++) {      // B: BN rows x 4 chunks
        int c = tid + (i << 8);
        int r = c >> 2, q = c & 3;
        uint32_t so = (uint32_t)(r * ROWB + q * 16);
        cpa16(st + TILE_A + so, Bm + (size_t)(bn + r) * K + k0 + (q << 3));
    }
}

template<int EPI, int BN, int MINB>
__global__ __launch_bounds__(256, MINB) void tgemm_kernel(
    const __half* __restrict__ A, const __half* __restrict__ Bm,
    const float* __restrict__ bias, const float* __restrict__ res,
    float* __restrict__ Cf, __half* __restrict__ Ch,
    int N, int K)
{
    constexpr int NT = BN / 32;          // n-tiles (8 wide) per warp
    constexpr int NP = NT / 2;           // ldmatrix groups (16 cols each)
    constexpr int TILE_A = 128 * ROWB;
    constexpr int TILE_B = BN * ROWB;
    constexpr int STAGE  = TILE_A + TILE_B;
    constexpr int WTN    = BN / 4;       // warptile n-width

    extern __shared__ __align__(1024) unsigned char smem[];
    uint32_t sb = smem_u32(smem);
    int tid = threadIdx.x, wid = tid >> 5, lane = tid & 31;
    int bm = blockIdx.x * 128, bn = blockIdx.y * BN;
    int wm = wid & 1, wn = wid >> 1;

    uint32_t a_lane = (uint32_t)((wm * 64 + (lane & 15)) * ROWB + ((lane >> 4) << 4));
    uint32_t b_lane = (uint32_t)(TILE_A + ((lane & 7) + ((lane >> 4) << 3)) * ROWB
                                 + (((lane >> 3) & 1) << 4));

    float acc[4][NT][4];
#pragma unroll
    for (int i = 0; i < 4; i++)
#pragma unroll
        for (int j = 0; j < NT; j++)
#pragma unroll
            for (int e = 0; e < 4; e++) acc[i][j][e] = 0.f;

    int nk = K >> 5;
    load_stage<BN>(sb,         A, Bm, bm, bn, 0,  K, tid); CP_COMMIT();
    load_stage<BN>(sb + STAGE, A, Bm, bm, bn, 32, K, tid); CP_COMMIT();

    uint32_t stg[3] = {sb, sb + STAGE, sb + 2 * STAGE};
    int cur = 0, nxt = 2;
    for (int kt = 0; kt < nk; kt++) {
        CP_WAIT1();
        __syncthreads();

        int kf = kt + 2;
        if (kf < nk)
            load_stage<BN>(stg[nxt], A, Bm, bm, bn, kf << 5, K, tid);
        CP_COMMIT();

        uint32_t st = stg[cur];
        cur = (cur + 1) % 3; nxt = (nxt + 1) % 3;
#pragma unroll
        for (int ks = 0; ks < 2; ks++) {
            uint32_t kb = ks << 5;
            Frag4 ah[4];
#pragma unroll
            for (int mt = 0; mt < 4; mt++)
                ah[mt] = ldsm_x4(st + a_lane + mt * (16 * ROWB) + kb);
#pragma unroll
            for (int np = 0; np < NP; np++) {
                Frag4 bf = ldsm_x4(st + b_lane + (wn * WTN + np * 16) * ROWB + kb);
#pragma unroll
                for (int mt = 0; mt < 4; mt++) {
                    mma_f16(acc[mt][np * 2],     ah[mt], bf.x, bf.y);
                    mma_f16(acc[mt][np * 2 + 1], ah[mt], bf.z, bf.w);
                }
            }
        }
    }
    __syncthreads();

    // Epilogue (register -> global)
    int row_in = lane >> 2;
    int col2   = (lane & 3) << 1;
#pragma unroll
    for (int mt = 0; mt < 4; mt++) {
#pragma unroll
        for (int nt = 0; nt < NT; nt++) {
            int col = bn + wn * WTN + nt * 8 + col2;
            float bx = bias[col], by = bias[col + 1];
#pragma unroll
            for (int half = 0; half < 2; half++) {
                int row = bm + wm * 64 + mt * 16 + row_in + half * 8;
                size_t off = (size_t)row * N + col;
                float v0 = acc[mt][nt][half * 2 + 0] + bx;
                float v1 = acc[mt][nt][half * 2 + 1] + by;
                if (EPI == 0) {
                    *(float2*)&Cf[off] = make_float2(v0, v1);
                } else if (EPI == 1) {
                    __half2 hh;
                    hh.x = __float2half(gelu_exact(v0));
                    hh.y = __float2half(gelu_exact(v1));
                    *(__half2*)&Ch[off] = hh;
                } else {
                    float2 rv = *(const float2*)&res[off];
                    *(float2*)&Cf[off] = make_float2(v0 + rv.x, v1 + rv.y);
                }
            }
        }
    }
}

#define SMEM256 (3 * (128 * ROWB + 256 * ROWB))   // 92160
#define SMEM128 (3 * (128 * ROWB + 128 * ROWB))   // 61440

// ---------------------------------------------------------------------------
// Weight transpose + fp16: W[K,N] (N contig) -> T[N,K] (K contig)
// ---------------------------------------------------------------------------
__global__ void wconv_kernel(const float* __restrict__ W,
                             __half* __restrict__ Th,
                             int K, int N, size_t inLs, size_t outLs)
{
    __shared__ float t[32][33];
    const float* Wl = W + blockIdx.z * inLs;
    Th += blockIdx.z * outLs;
    int n0 = blockIdx.x * 32, k0 = blockIdx.y * 32;
    int tx = threadIdx.x, ty = threadIdx.y;
#pragma unroll
    for (int i = 0; i < 4; i++)
        t[ty + 8 * i][tx] = Wl[(size_t)(k0 + ty + 8 * i) * N + n0 + tx];
    __syncthreads();
#pragma unroll
    for (int i = 0; i < 4; i++) {
        int n = ty + 8 * i;
        Th[(size_t)(n0 + n) * K + k0 + tx] = __float2half(t[tx][n]);
    }
}

// Merged QKV transpose: grid.z = l*3 + which
__global__ void wconv_qkv_kernel(const float* __restrict__ Wq,
                                 const float* __restrict__ Wk,
                                 const float* __restrict__ Wv,
                                 __half* __restrict__ Th)
{
    __shared__ float t[32][33];
    int l = blockIdx.z / 3, which = blockIdx.z % 3;
    const size_t EE = (size_t)E_ * E_;
    const float* Wl = (which == 0 ? Wq : which == 1 ? Wk : Wv) + l * EE;
    Th += (size_t)l * 3 * EE + (size_t)which * EE;
    int n0 = blockIdx.x * 32, k0 = blockIdx.y * 32;
    int tx = threadIdx.x, ty = threadIdx.y;
#pragma unroll
    for (int i = 0; i < 4; i++)
        t[ty + 8 * i][tx] = Wl[(size_t)(k0 + ty + 8 * i) * E_ + n0 + tx];
    __syncthreads();
#pragma unroll
    for (int i = 0; i < 4; i++) {
        int n = ty + 8 * i;
        Th[(size_t)(n0 + n) * E_ + k0 + tx] = __float2half(t[tx][n]);
    }
}

// Pack per-layer QKV biases into [L, 3E]
__global__ void bpack_kernel(const float* __restrict__ bq, const float* __restrict__ bk,
                             const float* __restrict__ bv, float* __restrict__ out) {
    int i = blockIdx.x * 256 + threadIdx.x;
    int l = i / 3072, j = i % 3072;
    float v = (j < 1024) ? bq[l * 1024 + j]
            : (j < 2048) ? bk[l * 1024 + j - 1024]
                         : bv[l * 1024 + j - 2048];
    out[i] = v;
}

// ---------------------------------------------------------------------------
// Embedding
// ---------------------------------------------------------------------------
__global__ void embed_kernel(const int* __restrict__ x, const float* __restrict__ tok,
                             const float* __restrict__ pos, float* __restrict__ h) {
    int i = blockIdx.x * 256 + threadIdx.x;
    int row = i >> 10, e = i & 1023;
    int tkn = x[row];
    int t = row & (T_ - 1);
    h[i] = tok[(size_t)tkn * E_ + e] + pos[(size_t)t * E_ + e];
}

// ---------------------------------------------------------------------------
// LayerNorm -> fp16
// ---------------------------------------------------------------------------
__global__ __launch_bounds__(256) void ln_kernel(const float* __restrict__ in,
                                                 const float* __restrict__ gam,
                                                 const float* __restrict__ bet,
                                                 __half* __restrict__ outh) {
    int row = blockIdx.x;
    const float* xr = in + (size_t)row * E_;
    float v0[4];
    float s = 0.f;
#pragma unroll
    for (int i = 0; i < 4; i++) { v0[i] = xr[threadIdx.x + 256 * i]; s += v0[i]; }

    __shared__ float sh[8];
    float t = s;
#pragma unroll
    for (int o = 16; o > 0; o >>= 1) t += __shfl_xor_sync(0xffffffffu, t, o);
    if ((threadIdx.x & 31) == 0) sh[threadIdx.x >> 5] = t;
    __syncthreads();
    float tot = 0.f;
#pragma unroll
    for (int i = 0; i < 8; i++) tot += sh[i];
    float mean = tot * (1.0f / E_);

    float vs = 0.f;
#pragma unroll
    for (int i = 0; i < 4; i++) { float d = v0[i] - mean; vs += d * d; }
    __syncthreads();
    t = vs;
#pragma unroll
    for (int o = 16; o > 0; o >>= 1) t += __shfl_xor_sync(0xffffffffu, t, o);
    if ((threadIdx.x & 31) == 0) sh[threadIdx.x >> 5] = t;
    __syncthreads();
    tot = 0.f;
#pragma unroll
    for (int i = 0; i < 8; i++) tot += sh[i];
    float rstd = rsqrtf(tot * (1.0f / E_) + 1e-5f);

#pragma unroll
    for (int i = 0; i < 4; i++) {
        int e = threadIdx.x + 256 * i;
        float y = (v0[i] - mean) * rstd * gam[e] + bet[e];
        outh[(size_t)row * E_ + e] = __float2half(y);
    }
}

// ---------------------------------------------------------------------------
// Causal flash attention, fp32. qkv packed [M, 3E]; out -> fp16 [M, E]
// ---------------------------------------------------------------------------
__global__ __launch_bounds__(64) void attn_kernel(const float* __restrict__ qkv,
                                                  __half* __restrict__ oh) {
    __shared__ float Ks[32][64];
    __shared__ float Vs[32][64];

    int qt = blockIdx.x & 31;
    int bh = blockIdx.x >> 5;
    int b  = bh >> 4;
    int hh = bh & 15;
    int row = qt * 64 + threadIdx.x;

    const float scale = 0.125f;
    float qr[64];
    const float* qp = qkv + (size_t)(b * T_ + row) * 3072 + hh * 64;
#pragma unroll
    for (int d = 0; d < 64; d++) qr[d] = qp[d] * scale;

    float acc[64];
#pragma unroll
    for (int d = 0; d < 64; d++) acc[d] = 0.f;
    float m = -1e30f, l = 0.f;

    int nt = qt * 2 + 2;
    for (int kt = 0; kt < nt; kt++) {
        int kb = kt * 32;
        {
            int tt = threadIdx.x;
#pragma unroll
            for (int i = 0; i < 8; i++) {
                int idx = (i * 64 + tt) * 4;
                int r = idx >> 6, c = idx & 63;
                size_t base = (size_t)(b * T_ + kb + r) * 3072 + hh * 64 + c;
                *(float4*)&Ks[r][c] = *(const float4*)(qkv + base + 1024);
                *(float4*)&Vs[r][c] = *(const float4*)(qkv + base + 2048);
            }
        }
        __syncthreads();

        float sv[32];
        float tmax = -1e30f;
#pragma unroll
        for (int c = 0; c < 32; c++) {
            if (kb + c <= row) {
                float sc = 0.f;
#pragma unroll
                for (int d = 0; d < 64; d += 4) {
                    float4 kv = *(const float4*)&Ks[c][d];
                    sc += qr[d] * kv.x + qr[d+1] * kv.y + qr[d+2] * kv.z + qr[d+3] * kv.w;
                }
                sv[c] = sc;
                tmax = fmaxf(tmax, sc);
            } else sv[c] = -1e30f;
        }
        float mnew = fmaxf(m, tmax);
        float corr = __expf(m - mnew);
        l *= corr;
#pragma unroll
        for (int d = 0; d < 64; d++) acc[d] *= corr;
#pragma unroll
        for (int c = 0; c < 32; c++) {
            float p = (kb + c <= row) ? __expf(sv[c] - mnew) : 0.f;
            l += p;
#pragma unroll
            for (int d = 0; d < 64; d += 4) {
                float4 vv = *(const float4*)&Vs[c][d];
                acc[d]   += p * vv.x;  acc[d+1] += p * vv.y;
                acc[d+2] += p * vv.z;  acc[d+3] += p * vv.w;
            }
        }
        m = mnew;
        __syncthreads();
    }

    float inv = 1.0f / l;
    size_t ob = (size_t)(b * T_ + row) * E_ + hh * 64;
#pragma unroll
    for (int d = 0; d < 64; d++)
        oh[ob + d] = __float2half(acc[d] * inv);
}

// ---------------------------------------------------------------------------
// Host orchestration
// ---------------------------------------------------------------------------
extern "C" void kernel_launch(void* const* d_in, const int* in_sizes, int n_in,
                              void* d_out, int out_size) {
    const int*   x    = (const int*)  d_in[0];
    const float* tok  = (const float*)d_in[1];
    const float* pos  = (const float*)d_in[2];
    const float* Wq   = (const float*)d_in[3];
    const float* bq   = (const float*)d_in[4];
    const float* Wk   = (const float*)d_in[5];
    const float* bk   = (const float*)d_in[6];
    const float* Wv   = (const float*)d_in[7];
    const float* bv   = (const float*)d_in[8];
    const float* Wo   = (const float*)d_in[9];
    const float* bo   = (const float*)d_in[10];
    const float* ln1g = (const float*)d_in[11];
    const float* ln1b = (const float*)d_in[12];
    const float* W1   = (const float*)d_in[13];
    const float* b1   = (const float*)d_in[14];
    const float* W2   = (const float*)d_in[15];
    const float* b2   = (const float*)d_in[16];
    const float* ln2g = (const float*)d_in[17];
    const float* ln2b = (const float*)d_in[18];
    const float* lnfg = (const float*)d_in[19];
    const float* lnfb = (const float*)d_in[20];
    const float* Wout = (const float*)d_in[21];
    const float* bout = (const float*)d_in[22];
    float* out = (float*)d_out;

    float *h, *qkv, *bqkv;
    __half *xn, *o, *mlp;
    __half *qkvT, *woT, *w1T, *w2T, *wouT;
    cudaGetSymbolAddress((void**)&h,    g_h);
    cudaGetSymbolAddress((void**)&qkv,  g_qkv);
    cudaGetSymbolAddress((void**)&bqkv, g_bqkv);
    cudaGetSymbolAddress((void**)&xn,   g_xn);
    cudaGetSymbolAddress((void**)&o,    g_o);
    cudaGetSymbolAddress((void**)&mlp,  g_mlp);
    cudaGetSymbolAddress((void**)&qkvT, g_qkvT);
    cudaGetSymbolAddress((void**)&woT,  g_woT);
    cudaGetSymbolAddress((void**)&w1T,  g_w1T);
    cudaGetSymbolAddress((void**)&w2T,  g_w2T);
    cudaGetSymbolAddress((void**)&wouT, g_woutT);

    cudaFuncSetAttribute((const void*)tgemm_kernel<0, 256, 1>, cudaFuncAttributeMaxDynamicSharedMemorySize, SMEM256);
    cudaFuncSetAttribute((const void*)tgemm_kernel<1, 256, 1>, cudaFuncAttributeMaxDynamicSharedMemorySize, SMEM256);
    cudaFuncSetAttribute((const void*)tgemm_kernel<2, 128, 2>, cudaFuncAttributeMaxDynamicSharedMemorySize, SMEM128);

    const size_t EE = (size_t)E_ * E_, EF = (size_t)E_ * F_;
    dim3 tb(32, 8);

    // Launch order arranged so launch index 5 is the first tgemm (ncu -s 5 -c 1)
    embed_kernel<<<(M_ * E_) / 256, 256>>>(x, tok, pos, h);                       // 0
    wconv_qkv_kernel<<<dim3(32, 32, 3 * L_), tb>>>(Wq, Wk, Wv, qkvT);             // 1
    bpack_kernel<<<(L_ * 3 * E_) / 256, 256>>>(bq, bk, bv, bqkv);                 // 2
    ln_kernel<<<M_, 256>>>(h, ln1g, ln1b, xn);                                    // 3 (layer 0)
    wconv_kernel<<<dim3(32, 32, L_), tb>>>(Wo, woT, E_, E_, EE, EE);              // 4
    tgemm_kernel<0, 256, 1><<<dim3(M_ / 128, 12), 256, SMEM256>>>(                // 5  <-- profiled
        xn, qkvT, bqkv, nullptr, qkv, nullptr, 3 * E_, E_);
    wconv_kernel<<<dim3(128, 32, L_), tb>>>(W1, w1T, E_, F_, EF, EF);             // 6
    wconv_kernel<<<dim3(32, 128, L_), tb>>>(W2, w2T, F_, E_, EF, EF);             // 7
    wconv_kernel<<<dim3(1000, 32, 1), tb>>>(Wout, wouT, E_, V_, 0, 0);            // 8

    for (int l = 0; l < L_; l++) {
        if (l > 0) {
            ln_kernel<<<M_, 256>>>(h, ln1g + l * E_, ln1b + l * E_, xn);
            tgemm_kernel<0, 256, 1><<<dim3(M_ / 128, 12), 256, SMEM256>>>(
                xn, qkvT + l * 3 * EE, bqkv + l * 3 * E_, nullptr, qkv, nullptr, 3 * E_, E_);
        }
        attn_kernel<<<B_ * H_ * (T_ / 64), 64>>>(qkv, o);
        tgemm_kernel<2, 128, 2><<<dim3(M_ / 128, 8), 256, SMEM128>>>(
            o, woT + l * EE, bo + l * E_, h, h, nullptr, E_, E_);
        ln_kernel<<<M_, 256>>>(h, ln2g + l * E_, ln2b + l * E_, xn);
        tgemm_kernel<1, 256, 1><<<dim3(M_ / 128, 16), 256, SMEM256>>>(
            xn, w1T + l * EF, b1 + l * F_, nullptr, nullptr, mlp, F_, E_);
        tgemm_kernel<2, 128, 2><<<dim3(M_ / 128, 8), 256, SMEM128>>>(
            mlp, w2T + l * EF, b2 + l * E_, h, h, nullptr, E_, F_);
    }

    ln_kernel<<<M_, 256>>>(h, lnfg, lnfb, xn);
    tgemm_kernel<0, 256, 1><<<dim3(M_ / 128, V_ / 256), 256, SMEM256>>>(
        xn, wouT, bout, nullptr, out, nullptr, V_, E_);
}

// round 7
// speedup vs baseline: 2.3833x; 1.0627x over previous
#include <cuda_runtime.h>
#include <cuda_fp16.h>
#include <math.h>
#include <stdint.h>

// Problem dims
#define V_ 32000
#define E_ 1024
#define H_ 16
#define F_ 4096
#define L_ 4
#define T_ 2048
#define B_ 2
#define D_ 64
#define M_ (B_*T_)   // 4096

// ---------------------------------------------------------------------------
// Scratch (device globals; allocation APIs are forbidden)
// ---------------------------------------------------------------------------
__device__ float g_h  [M_*E_];
__device__ float g_qkv[M_*3*E_];
__device__ float g_bqkv[L_*3*E_];
__device__ __half g_xn [M_*E_];
__device__ __half g_o  [M_*E_];
__device__ __half g_mlp[M_*F_];
__device__ __half g_qkvT[L_*3*E_*E_];
__device__ __half g_woT [L_*E_*E_];
__device__ __half g_w1T [L_*F_*E_];
__device__ __half g_w2T [L_*E_*F_];
__device__ __half g_woutT[(size_t)V_*E_];

// ---------------------------------------------------------------------------
// PTX helpers
// ---------------------------------------------------------------------------
__device__ __forceinline__ uint32_t smem_u32(const void* p) {
    uint32_t a;
    asm("{ .reg .u64 t; cvta.to.shared.u64 t, %1; cvt.u32.u64 %0, t; }" : "=r"(a) : "l"(p));
    return a;
}
static __device__ __forceinline__ void cpa16(uint32_t s, const void* g) {
    asm volatile("cp.async.cg.shared.global [%0], [%1], 16;" :: "r"(s), "l"(g) : "memory");
}
#define CP_COMMIT() asm volatile("cp.async.commit_group;" ::: "memory")
#define CP_WAIT1()  asm volatile("cp.async.wait_group 1;" ::: "memory")

struct Frag4 { uint32_t x, y, z, w; };

static __device__ __forceinline__ Frag4 ldsm_x4(uint32_t addr) {
    Frag4 r;
    asm volatile("ldmatrix.sync.aligned.m8n8.x4.shared.b16 {%0,%1,%2,%3}, [%4];"
                 : "=r"(r.x), "=r"(r.y), "=r"(r.z), "=r"(r.w) : "r"(addr));
    return r;
}

static __device__ __forceinline__ void mma_f16(float* c, const Frag4& a,
                                               uint32_t b0, uint32_t b1) {
    asm volatile(
        "mma.sync.aligned.m16n8k16.row.col.f32.f16.f16.f32 "
        "{%0,%1,%2,%3}, {%4,%5,%6,%7}, {%8,%9}, {%0,%1,%2,%3};"
        : "+f"(c[0]), "+f"(c[1]), "+f"(c[2]), "+f"(c[3])
        : "r"(a.x), "r"(a.y), "r"(a.z), "r"(a.w), "r"(b0), "r"(b1));
}

__device__ __forceinline__ float gelu_exact(float x) {
    return 0.5f * x * (1.0f + erff(x * 0.70710678118654752f));
}

// ---------------------------------------------------------------------------
// HMMA GEMM: C[M,N] = A[M,K] @ B^T   (A, B fp16; B stored [N,K], K-contig)
// Single-term fp16 MMA, fp32 accum.
// BM=128, BN=128, BK=64, 3-stage cp.async, 256 threads (8 warps 2x4),
// 2 CTAs/SM (reg cap 128). warptile 64x32. ROWB=144 -> conflict-free ldsm.
// EPI: 0 = fp32 +bias ; 1 = gelu -> fp16 ; 2 = fp32 +bias +residual
// ---------------------------------------------------------------------------
#define ROWB    144
#define TILE_A  (128 * ROWB)          // 18432
#define STAGE_B (2 * TILE_A)          // 36864
#define SMEM_G  (3 * STAGE_B)         // 110592

static __device__ __forceinline__ void load_stage(
    uint32_t st, const __half* __restrict__ A, const __half* __restrict__ Bm,
    int bm, int bn, int k0, int K, int tid)
{
#pragma unroll
    for (int i = 0; i < 4; i++) {            // A: 128 rows x 8 chunks = 1024
        int c = tid + (i << 8);
        int r = c >> 3, q = c & 7;
        uint32_t so = (uint32_t)(r * ROWB + q * 16);
        cpa16(st + so, A + (size_t)(bm + r) * K + k0 + (q << 3));
    }
#pragma unroll
    for (int i = 0; i < 4; i++) {            // B: 128 rows x 8 chunks
        int c = tid + (i << 8);
        int r = c >> 3, q = c & 7;
        uint32_t so = (uint32_t)(r * ROWB + q * 16);
        cpa16(st + TILE_A + so, Bm + (size_t)(bn + r) * K + k0 + (q << 3));
    }
}

template<int EPI>
__global__ __launch_bounds__(256, 2) void tgemm_kernel(
    const __half* __restrict__ A, const __half* __restrict__ Bm,
    const float* __restrict__ bias, const float* __restrict__ res,
    float* __restrict__ Cf, __half* __restrict__ Ch,
    int N, int K)
{
    extern __shared__ __align__(1024) unsigned char smem[];
    uint32_t sb = smem_u32(smem);
    int tid = threadIdx.x, wid = tid >> 5, lane = tid & 31;
    int bm = blockIdx.x * 128, bn = blockIdx.y * 128;
    int wm = wid & 1, wn = wid >> 1;

    uint32_t a_lane = (uint32_t)((wm * 64 + (lane & 15)) * ROWB + ((lane >> 4) << 4));
    uint32_t b_lane = (uint32_t)(TILE_A + ((lane & 7) + ((lane >> 4) << 3)) * ROWB
                                 + (((lane >> 3) & 1) << 4));

    float acc[4][4][4];
#pragma unroll
    for (int i = 0; i < 4; i++)
#pragma unroll
        for (int j = 0; j < 4; j++)
#pragma unroll
            for (int e = 0; e < 4; e++) acc[i][j][e] = 0.f;

    int nk = K >> 6;
    load_stage(sb,           A, Bm, bm, bn, 0,  K, tid); CP_COMMIT();
    load_stage(sb + STAGE_B, A, Bm, bm, bn, 64, K, tid); CP_COMMIT();

    uint32_t stg[3] = {sb, sb + STAGE_B, sb + 2 * STAGE_B};
    int cur = 0, nxt = 2;
    for (int kt = 0; kt < nk; kt++) {
        CP_WAIT1();
        __syncthreads();

        int kf = kt + 2;
        if (kf < nk)
            load_stage(stg[nxt], A, Bm, bm, bn, kf << 6, K, tid);
        CP_COMMIT();

        uint32_t st = stg[cur];
        cur = (cur + 1) % 3; nxt = (nxt + 1) % 3;
#pragma unroll
        for (int ks = 0; ks < 4; ks++) {
            uint32_t kb = ks << 5;   // 16 fp16 = 32 bytes per k-step
            Frag4 ah[4];
#pragma unroll
            for (int mt = 0; mt < 4; mt++)
                ah[mt] = ldsm_x4(st + a_lane + mt * (16 * ROWB) + kb);
#pragma unroll
            for (int np = 0; np < 2; np++) {
                Frag4 bf = ldsm_x4(st + b_lane + (wn * 32 + np * 16) * ROWB + kb);
#pragma unroll
                for (int mt = 0; mt < 4; mt++) {
                    mma_f16(acc[mt][np * 2],     ah[mt], bf.x, bf.y);
                    mma_f16(acc[mt][np * 2 + 1], ah[mt], bf.z, bf.w);
                }
            }
        }
    }
    __syncthreads();

    // Epilogue (register -> global)
    int row_in = lane >> 2;
    int col2   = (lane & 3) << 1;
#pragma unroll
    for (int mt = 0; mt < 4; mt++) {
#pragma unroll
        for (int nt = 0; nt < 4; nt++) {
            int col = bn + wn * 32 + nt * 8 + col2;
            float bx = bias[col], by = bias[col + 1];
#pragma unroll
            for (int half = 0; half < 2; half++) {
                int row = bm + wm * 64 + mt * 16 + row_in + half * 8;
                size_t off = (size_t)row * N + col;
                float v0 = acc[mt][nt][half * 2 + 0] + bx;
                float v1 = acc[mt][nt][half * 2 + 1] + by;
                if (EPI == 0) {
                    *(float2*)&Cf[off] = make_float2(v0, v1);
                } else if (EPI == 1) {
                    __half2 hh;
                    hh.x = __float2half(gelu_exact(v0));
                    hh.y = __float2half(gelu_exact(v1));
                    *(__half2*)&Ch[off] = hh;
                } else {
                    float2 rv = *(const float2*)&res[off];
                    *(float2*)&Cf[off] = make_float2(v0 + rv.x, v1 + rv.y);
                }
            }
        }
    }
}

// ---------------------------------------------------------------------------
// Weight transpose + fp16: W[K,N] (N contig) -> T[N,K] (K contig)
// ---------------------------------------------------------------------------
__global__ void wconv_kernel(const float* __restrict__ W,
                             __half* __restrict__ Th,
                             int K, int N, size_t inLs, size_t outLs)
{
    __shared__ float t[32][33];
    const float* Wl = W + blockIdx.z * inLs;
    Th += blockIdx.z * outLs;
    int n0 = blockIdx.x * 32, k0 = blockIdx.y * 32;
    int tx = threadIdx.x, ty = threadIdx.y;
#pragma unroll
    for (int i = 0; i < 4; i++)
        t[ty + 8 * i][tx] = Wl[(size_t)(k0 + ty + 8 * i) * N + n0 + tx];
    __syncthreads();
#pragma unroll
    for (int i = 0; i < 4; i++) {
        int n = ty + 8 * i;
        Th[(size_t)(n0 + n) * K + k0 + tx] = __float2half(t[tx][n]);
    }
}

// Merged QKV transpose: grid.z = l*3 + which
__global__ void wconv_qkv_kernel(const float* __restrict__ Wq,
                                 const float* __restrict__ Wk,
                                 const float* __restrict__ Wv,
                                 __half* __restrict__ Th)
{
    __shared__ float t[32][33];
    int l = blockIdx.z / 3, which = blockIdx.z % 3;
    const size_t EE = (size_t)E_ * E_;
    const float* Wl = (which == 0 ? Wq : which == 1 ? Wk : Wv) + l * EE;
    Th += (size_t)l * 3 * EE + (size_t)which * EE;
    int n0 = blockIdx.x * 32, k0 = blockIdx.y * 32;
    int tx = threadIdx.x, ty = threadIdx.y;
#pragma unroll
    for (int i = 0; i < 4; i++)
        t[ty + 8 * i][tx] = Wl[(size_t)(k0 + ty + 8 * i) * E_ + n0 + tx];
    __syncthreads();
#pragma unroll
    for (int i = 0; i < 4; i++) {
        int n = ty + 8 * i;
        Th[(size_t)(n0 + n) * E_ + k0 + tx] = __float2half(t[tx][n]);
    }
}

// Pack per-layer QKV biases into [L, 3E]
__global__ void bpack_kernel(const float* __restrict__ bq, const float* __restrict__ bk,
                             const float* __restrict__ bv, float* __restrict__ out) {
    int i = blockIdx.x * 256 + threadIdx.x;
    int l = i / 3072, j = i % 3072;
    float v = (j < 1024) ? bq[l * 1024 + j]
            : (j < 2048) ? bk[l * 1024 + j - 1024]
                         : bv[l * 1024 + j - 2048];
    out[i] = v;
}

// ---------------------------------------------------------------------------
// Embedding
// ---------------------------------------------------------------------------
__global__ void embed_kernel(const int* __restrict__ x, const float* __restrict__ tok,
                             const float* __restrict__ pos, float* __restrict__ h) {
    int i = blockIdx.x * 256 + threadIdx.x;
    int row = i >> 10, e = i & 1023;
    int tkn = x[row];
    int t = row & (T_ - 1);
    h[i] = tok[(size_t)tkn * E_ + e] + pos[(size_t)t * E_ + e];
}

// ---------------------------------------------------------------------------
// LayerNorm -> fp16
// ---------------------------------------------------------------------------
__global__ __launch_bounds__(256) void ln_kernel(const float* __restrict__ in,
                                                 const float* __restrict__ gam,
                                                 const float* __restrict__ bet,
                                                 __half* __restrict__ outh) {
    int row = blockIdx.x;
    const float* xr = in + (size_t)row * E_;
    float v0[4];
    float s = 0.f;
#pragma unroll
    for (int i = 0; i < 4; i++) { v0[i] = xr[threadIdx.x + 256 * i]; s += v0[i]; }

    __shared__ float sh[8];
    float t = s;
#pragma unroll
    for (int o = 16; o > 0; o >>= 1) t += __shfl_xor_sync(0xffffffffu, t, o);
    if ((threadIdx.x & 31) == 0) sh[threadIdx.x >> 5] = t;
    __syncthreads();
    float tot = 0.f;
#pragma unroll
    for (int i = 0; i < 8; i++) tot += sh[i];
    float mean = tot * (1.0f / E_);

    float vs = 0.f;
#pragma unroll
    for (int i = 0; i < 4; i++) { float d = v0[i] - mean; vs += d * d; }
    __syncthreads();
    t = vs;
#pragma unroll
    for (int o = 16; o > 0; o >>= 1) t += __shfl_xor_sync(0xffffffffu, t, o);
    if ((threadIdx.x & 31) == 0) sh[threadIdx.x >> 5] = t;
    __syncthreads();
    tot = 0.f;
#pragma unroll
    for (int i = 0; i < 8; i++) tot += sh[i];
    float rstd = rsqrtf(tot * (1.0f / E_) + 1e-5f);

#pragma unroll
    for (int i = 0; i < 4; i++) {
        int e = threadIdx.x + 256 * i;
        float y = (v0[i] - mean) * rstd * gam[e] + bet[e];
        outh[(size_t)row * E_ + e] = __float2half(y);
    }
}

// ---------------------------------------------------------------------------
// Causal flash attention, fp32. qkv packed [M, 3E]; out -> fp16 [M, E]
// ---------------------------------------------------------------------------
__global__ __launch_bounds__(64) void attn_kernel(const float* __restrict__ qkv,
                                                  __half* __restrict__ oh) {
    __shared__ float Ks[32][64];
    __shared__ float Vs[32][64];

    int qt = blockIdx.x & 31;
    int bh = blockIdx.x >> 5;
    int b  = bh >> 4;
    int hh = bh & 15;
    int row = qt * 64 + threadIdx.x;

    const float scale = 0.125f;
    float qr[64];
    const float* qp = qkv + (size_t)(b * T_ + row) * 3072 + hh * 64;
#pragma unroll
    for (int d = 0; d < 64; d++) qr[d] = qp[d] * scale;

    float acc[64];
#pragma unroll
    for (int d = 0; d < 64; d++) acc[d] = 0.f;
    float m = -1e30f, l = 0.f;

    int nt = qt * 2 + 2;
    for (int kt = 0; kt < nt; kt++) {
        int kb = kt * 32;
        {
            int tt = threadIdx.x;
#pragma unroll
            for (int i = 0; i < 8; i++) {
                int idx = (i * 64 + tt) * 4;
                int r = idx >> 6, c = idx & 63;
                size_t base = (size_t)(b * T_ + kb + r) * 3072 + hh * 64 + c;
                *(float4*)&Ks[r][c] = *(const float4*)(qkv + base + 1024);
                *(float4*)&Vs[r][c] = *(const float4*)(qkv + base + 2048);
            }
        }
        __syncthreads();

        float sv[32];
        float tmax = -1e30f;
#pragma unroll
        for (int c = 0; c < 32; c++) {
            if (kb + c <= row) {
                float sc = 0.f;
#pragma unroll
                for (int d = 0; d < 64; d += 4) {
                    float4 kv = *(const float4*)&Ks[c][d];
                    sc += qr[d] * kv.x + qr[d+1] * kv.y + qr[d+2] * kv.z + qr[d+3] * kv.w;
                }
                sv[c] = sc;
                tmax = fmaxf(tmax, sc);
            } else sv[c] = -1e30f;
        }
        float mnew = fmaxf(m, tmax);
        float corr = __expf(m - mnew);
        l *= corr;
#pragma unroll
        for (int d = 0; d < 64; d++) acc[d] *= corr;
#pragma unroll
        for (int c = 0; c < 32; c++) {
            float p = (kb + c <= row) ? __expf(sv[c] - mnew) : 0.f;
            l += p;
#pragma unroll
            for (int d = 0; d < 64; d += 4) {
                float4 vv = *(const float4*)&Vs[c][d];
                acc[d]   += p * vv.x;  acc[d+1] += p * vv.y;
                acc[d+2] += p * vv.z;  acc[d+3] += p * vv.w;
            }
        }
        m = mnew;
        __syncthreads();
    }

    float inv = 1.0f / l;
    size_t ob = (size_t)(b * T_ + row) * E_ + hh * 64;
#pragma unroll
    for (int d = 0; d < 64; d++)
        oh[ob + d] = __float2half(acc[d] * inv);
}

// ---------------------------------------------------------------------------
// Host orchestration
// ---------------------------------------------------------------------------
extern "C" void kernel_launch(void* const* d_in, const int* in_sizes, int n_in,
                              void* d_out, int out_size) {
    const int*   x    = (const int*)  d_in[0];
    const float* tok  = (const float*)d_in[1];
    const float* pos  = (const float*)d_in[2];
    const float* Wq   = (const float*)d_in[3];
    const float* bq   = (const float*)d_in[4];
    const float* Wk   = (const float*)d_in[5];
    const float* bk   = (const float*)d_in[6];
    const float* Wv   = (const float*)d_in[7];
    const float* bv   = (const float*)d_in[8];
    const float* Wo   = (const float*)d_in[9];
    const float* bo   = (const float*)d_in[10];
    const float* ln1g = (const float*)d_in[11];
    const float* ln1b = (const float*)d_in[12];
    const float* W1   = (const float*)d_in[13];
    const float* b1   = (const float*)d_in[14];
    const float* W2   = (const float*)d_in[15];
    const float* b2   = (const float*)d_in[16];
    const float* ln2g = (const float*)d_in[17];
    const float* ln2b = (const float*)d_in[18];
    const float* lnfg = (const float*)d_in[19];
    const float* lnfb = (const float*)d_in[20];
    const float* Wout = (const float*)d_in[21];
    const float* bout = (const float*)d_in[22];
    float* out = (float*)d_out;

    float *h, *qkv, *bqkv;
    __half *xn, *o, *mlp;
    __half *qkvT, *woT, *w1T, *w2T, *wouT;
    cudaGetSymbolAddress((void**)&h,    g_h);
    cudaGetSymbolAddress((void**)&qkv,  g_qkv);
    cudaGetSymbolAddress((void**)&bqkv, g_bqkv);
    cudaGetSymbolAddress((void**)&xn,   g_xn);
    cudaGetSymbolAddress((void**)&o,    g_o);
    cudaGetSymbolAddress((void**)&mlp,  g_mlp);
    cudaGetSymbolAddress((void**)&qkvT, g_qkvT);
    cudaGetSymbolAddress((void**)&woT,  g_woT);
    cudaGetSymbolAddress((void**)&w1T,  g_w1T);
    cudaGetSymbolAddress((void**)&w2T,  g_w2T);
    cudaGetSymbolAddress((void**)&wouT, g_woutT);

    cudaFuncSetAttribute((const void*)tgemm_kernel<0>, cudaFuncAttributeMaxDynamicSharedMemorySize, SMEM_G);
    cudaFuncSetAttribute((const void*)tgemm_kernel<1>, cudaFuncAttributeMaxDynamicSharedMemorySize, SMEM_G);
    cudaFuncSetAttribute((const void*)tgemm_kernel<2>, cudaFuncAttributeMaxDynamicSharedMemorySize, SMEM_G);

    const size_t EE = (size_t)E_ * E_, EF = (size_t)E_ * F_;
    dim3 tb(32, 8);

    // Launch order arranged so launch index 5 is the first tgemm (ncu -s 5 -c 1)
    embed_kernel<<<(M_ * E_) / 256, 256>>>(x, tok, pos, h);                       // 0
    wconv_qkv_kernel<<<dim3(32, 32, 3 * L_), tb>>>(Wq, Wk, Wv, qkvT);             // 1
    bpack_kernel<<<(L_ * 3 * E_) / 256, 256>>>(bq, bk, bv, bqkv);                 // 2
    ln_kernel<<<M_, 256>>>(h, ln1g, ln1b, xn);                                    // 3 (layer 0)
    wconv_kernel<<<dim3(32, 32, L_), tb>>>(Wo, woT, E_, E_, EE, EE);              // 4
    tgemm_kernel<0><<<dim3(M_ / 128, 24), 256, SMEM_G>>>(                         // 5  <-- profiled
        xn, qkvT, bqkv, nullptr, qkv, nullptr, 3 * E_, E_);
    wconv_kernel<<<dim3(128, 32, L_), tb>>>(W1, w1T, E_, F_, EF, EF);             // 6
    wconv_kernel<<<dim3(32, 128, L_), tb>>>(W2, w2T, F_, E_, EF, EF);             // 7
    wconv_kernel<<<dim3(1000, 32, 1), tb>>>(Wout, wouT, E_, V_, 0, 0);            // 8

    for (int l = 0; l < L_; l++) {
        if (l > 0) {
            ln_kernel<<<M_, 256>>>(h, ln1g + l * E_, ln1b + l * E_, xn);
            tgemm_kernel<0><<<dim3(M_ / 128, 24), 256, SMEM_G>>>(
                xn, qkvT + l * 3 * EE, bqkv + l * 3 * E_, nullptr, qkv, nullptr, 3 * E_, E_);
        }
        attn_kernel<<<B_ * H_ * (T_ / 64), 64>>>(qkv, o);
        tgemm_kernel<2><<<dim3(M_ / 128, 8), 256, SMEM_G>>>(
            o, woT + l * EE, bo + l * E_, h, h, nullptr, E_, E_);
        ln_kernel<<<M_, 256>>>(h, ln2g + l * E_, ln2b + l * E_, xn);
        tgemm_kernel<1><<<dim3(M_ / 128, 32), 256, SMEM_G>>>(
            xn, w1T + l * EF, b1 + l * F_, nullptr, nullptr, mlp, F_, E_);
        tgemm_kernel<2><<<dim3(M_ / 128, 8), 256, SMEM_G>>>(
            mlp, w2T + l * EF, b2 + l * E_, h, h, nullptr, E_, F_);
    }

    ln_kernel<<<M_, 256>>>(h, lnfg, lnfb, xn);
    tgemm_kernel<0><<<dim3(M_ / 128, V_ / 128), 256, SMEM_G>>>(
        xn, wouT, bout, nullptr, out, nullptr, V_, E_);
}